// round 5
// baseline (speedup 1.0000x reference)
#include <cuda_runtime.h>
#include <cuda_bf16.h>
#include <math.h>

#define SEQ   2048
#define HID   2048
#define NH    32
#define KVH   8
#define HD    64
#define QKVD  3072   // (NH + 2*KVH) * HD

// Scratch (alloc-free rule: device globals)
__device__ float g_qkv[SEQ * QKVD];   // [s, 3072] : q | k | v
__device__ float g_attn[SEQ * HID];   // [s, NH*HD]

// ---------------------------------------------------------------------------
// SGEMM: C[M,N] = A[M,K] * B[N,K]^T   (both row-major, K contiguous)
// 128x128 tile, BK=8, 256 threads, 8x8 micro-tile per thread.
// ---------------------------------------------------------------------------
__global__ __launch_bounds__(256) void sgemm_nt(
    const float* __restrict__ A, const float* __restrict__ B,
    float* __restrict__ C, int M, int N, int K)
{
    __shared__ float As[8 * 128];   // As[k][row]
    __shared__ float Bs[8 * 128];   // Bs[k][col]

    const int t  = threadIdx.x;
    const int m0 = blockIdx.y * 128;
    const int n0 = blockIdx.x * 128;
    const int tr = t >> 4;          // 0..15 -> rows tr*8..tr*8+7
    const int tc = t & 15;          // 0..15 -> cols tc*8..tc*8+7
    const int lrow = t >> 1;        // 0..127
    const int lk   = (t & 1) * 4;   // 0 or 4

    float acc[8][8];
#pragma unroll
    for (int i = 0; i < 8; i++)
#pragma unroll
        for (int j = 0; j < 8; j++) acc[i][j] = 0.f;

    const float* Ap = A + (size_t)(m0 + lrow) * K + lk;
    const float* Bp = B + (size_t)(n0 + lrow) * K + lk;

    for (int kb = 0; kb < K; kb += 8) {
        float4 av = *(const float4*)(Ap + kb);
        float4 bv = *(const float4*)(Bp + kb);
        __syncthreads();
        As[(lk + 0) * 128 + lrow] = av.x;
        As[(lk + 1) * 128 + lrow] = av.y;
        As[(lk + 2) * 128 + lrow] = av.z;
        As[(lk + 3) * 128 + lrow] = av.w;
        Bs[(lk + 0) * 128 + lrow] = bv.x;
        Bs[(lk + 1) * 128 + lrow] = bv.y;
        Bs[(lk + 2) * 128 + lrow] = bv.z;
        Bs[(lk + 3) * 128 + lrow] = bv.w;
        __syncthreads();
#pragma unroll
        for (int k = 0; k < 8; k++) {
            float4 a0 = *(const float4*)(As + k * 128 + tr * 8);
            float4 a1 = *(const float4*)(As + k * 128 + tr * 8 + 4);
            float4 b0 = *(const float4*)(Bs + k * 128 + tc * 8);
            float4 b1 = *(const float4*)(Bs + k * 128 + tc * 8 + 4);
            float a[8] = {a0.x, a0.y, a0.z, a0.w, a1.x, a1.y, a1.z, a1.w};
            float b[8] = {b0.x, b0.y, b0.z, b0.w, b1.x, b1.y, b1.z, b1.w};
#pragma unroll
            for (int i = 0; i < 8; i++)
#pragma unroll
                for (int j = 0; j < 8; j++)
                    acc[i][j] = fmaf(a[i], b[j], acc[i][j]);
        }
    }

#pragma unroll
    for (int i = 0; i < 8; i++) {
        float* cp = C + (size_t)(m0 + tr * 8 + i) * N + n0 + tc * 8;
        float4 o0 = make_float4(acc[i][0], acc[i][1], acc[i][2], acc[i][3]);
        float4 o1 = make_float4(acc[i][4], acc[i][5], acc[i][6], acc[i][7]);
        *(float4*)(cp)     = o0;
        *(float4*)(cp + 4) = o1;
    }
}

// ---------------------------------------------------------------------------
// RoPE in-place on q (32 heads) and k (8 heads) sections of g_qkv.
// Matches reference fp32 math: inv_freq = 10000^(-i/32), pairs (i, i+32).
// ---------------------------------------------------------------------------
__global__ void rope_kernel(float* __restrict__ qkv)
{
    int idx = blockIdx.x * blockDim.x + threadIdx.x;
    const int total = SEQ * (NH + KVH) * 32;
    if (idx >= total) return;
    int i  = idx & 31;
    int hh = (idx >> 5) % (NH + KVH);
    int s  = idx / ((NH + KVH) * 32);
    size_t base = (size_t)s * QKVD + (hh < NH ? hh * HD : NH * HD + (hh - NH) * HD);
    float inv_freq = 1.0f / powf(10000.0f, (float)i / 32.0f);
    float ang = (float)s * inv_freq;
    float sn, cs;
    sincosf(ang, &sn, &cs);
    float x1 = qkv[base + i];
    float x2 = qkv[base + 32 + i];
    qkv[base + i]      = x1 * cs - x2 * sn;
    qkv[base + 32 + i] = x2 * cs + x1 * sn;
}

// ---------------------------------------------------------------------------
// Causal flash attention, fp32, GQA (G=4). BM=BN=64, D=64, 256 threads.
// Thread (tr,tc) owns rows {tr+16i} and cols {tc+16j} (strided -> conflict-free
// SMEM reads). V stored transposed so PV has the same dot structure as QK.
// ---------------------------------------------------------------------------
#define PAD 68   // row stride (floats), keeps float4 alignment + spreads banks

__global__ __launch_bounds__(256, 2) void flash_attn(
    const float* __restrict__ qkv, float* __restrict__ out)
{
    extern __shared__ float sm[];
    float* Qs = sm;                 // [64][PAD]  Q rows, d contiguous
    float* Ks = sm + 64 * PAD;      // [64][PAD]  K rows, d contiguous
    float* Vt = sm + 2 * 64 * PAD;  // [64][PAD]  V transposed: [d][kv]
    float* Ps = sm + 3 * 64 * PAD;  // [64][PAD]  probabilities

    const int qt = blockIdx.x;      // query tile (64 rows)
    const int h  = blockIdx.y;      // q head
    const int kh = h >> 2;          // kv head (G=4)
    const int t  = threadIdx.x;
    const int tr = t >> 4;          // 0..15
    const int tc = t & 15;          // 0..15
    const int lr = t >> 2;          // loader row 0..63
    const int lc = (t & 3) * 16;    // loader col base

    // Load Q tile
    {
        const float* qp = qkv + (size_t)(qt * 64 + lr) * QKVD + h * HD + lc;
#pragma unroll
        for (int j = 0; j < 4; j++)
            *(float4*)(Qs + lr * PAD + lc + 4 * j) = *(const float4*)(qp + 4 * j);
    }

    float o[4][4];
    float mi[4], li[4];
#pragma unroll
    for (int i = 0; i < 4; i++) {
        mi[i] = -1e30f; li[i] = 0.f;
#pragma unroll
        for (int j = 0; j < 4; j++) o[i][j] = 0.f;
    }

    __syncthreads();

    for (int jt = 0; jt <= qt; ++jt) {
        // Load K tile and V tile (transposed)
        {
            const float* kp = qkv + (size_t)(jt * 64 + lr) * QKVD + NH * HD + kh * HD + lc;
            const float* vp = qkv + (size_t)(jt * 64 + lr) * QKVD + (NH + KVH) * HD + kh * HD + lc;
#pragma unroll
            for (int j = 0; j < 4; j++) {
                *(float4*)(Ks + lr * PAD + lc + 4 * j) = *(const float4*)(kp + 4 * j);
                float4 vv = *(const float4*)(vp + 4 * j);
                Vt[(lc + 4 * j + 0) * PAD + lr] = vv.x;
                Vt[(lc + 4 * j + 1) * PAD + lr] = vv.y;
                Vt[(lc + 4 * j + 2) * PAD + lr] = vv.z;
                Vt[(lc + 4 * j + 3) * PAD + lr] = vv.w;
            }
        }
        __syncthreads();

        // Scores: s[i][j] = Q[tr+16i] . K[tc+16j]
        float s[4][4];
#pragma unroll
        for (int i = 0; i < 4; i++)
#pragma unroll
            for (int j = 0; j < 4; j++) s[i][j] = 0.f;

#pragma unroll
        for (int k4 = 0; k4 < 16; k4++) {
            float4 qv[4], kv4[4];
#pragma unroll
            for (int i = 0; i < 4; i++)
                qv[i] = *(const float4*)(Qs + (tr + 16 * i) * PAD + 4 * k4);
#pragma unroll
            for (int j = 0; j < 4; j++)
                kv4[j] = *(const float4*)(Ks + (tc + 16 * j) * PAD + 4 * k4);
#pragma unroll
            for (int i = 0; i < 4; i++)
#pragma unroll
                for (int j = 0; j < 4; j++)
                    s[i][j] += qv[i].x * kv4[j].x + qv[i].y * kv4[j].y
                             + qv[i].z * kv4[j].z + qv[i].w * kv4[j].w;
        }

        // Scale + causal mask (diagonal tile only)
        const float scale = 0.125f;  // 1/sqrt(64)
        if (jt == qt) {
#pragma unroll
            for (int i = 0; i < 4; i++)
#pragma unroll
                for (int j = 0; j < 4; j++) {
                    int r = tr + 16 * i, c = tc + 16 * j;
                    s[i][j] = (c <= r) ? s[i][j] * scale : -1e30f;
                }
        } else {
#pragma unroll
            for (int i = 0; i < 4; i++)
#pragma unroll
                for (int j = 0; j < 4; j++) s[i][j] *= scale;
        }

        // Online softmax update (row group = 16 lanes sharing tr)
#pragma unroll
        for (int i = 0; i < 4; i++) {
            float mt = fmaxf(fmaxf(s[i][0], s[i][1]), fmaxf(s[i][2], s[i][3]));
            mt = fmaxf(mt, __shfl_xor_sync(0xffffffffu, mt, 1));
            mt = fmaxf(mt, __shfl_xor_sync(0xffffffffu, mt, 2));
            mt = fmaxf(mt, __shfl_xor_sync(0xffffffffu, mt, 4));
            mt = fmaxf(mt, __shfl_xor_sync(0xffffffffu, mt, 8));
            float mnew  = fmaxf(mi[i], mt);
            float alpha = __expf(mi[i] - mnew);
            float rs = 0.f;
#pragma unroll
            for (int j = 0; j < 4; j++) {
                float p = __expf(s[i][j] - mnew);
                Ps[(tr + 16 * i) * PAD + tc + 16 * j] = p;
                rs += p;
            }
            rs += __shfl_xor_sync(0xffffffffu, rs, 1);
            rs += __shfl_xor_sync(0xffffffffu, rs, 2);
            rs += __shfl_xor_sync(0xffffffffu, rs, 4);
            rs += __shfl_xor_sync(0xffffffffu, rs, 8);
            li[i] = li[i] * alpha + rs;
            mi[i] = mnew;
#pragma unroll
            for (int j = 0; j < 4; j++) o[i][j] *= alpha;
        }
        __syncthreads();

        // PV: o[i][j] += P[tr+16i][:] . Vt[tc+16j][:]
#pragma unroll
        for (int k4 = 0; k4 < 16; k4++) {
            float4 pv[4], vv[4];
#pragma unroll
            for (int i = 0; i < 4; i++)
                pv[i] = *(const float4*)(Ps + (tr + 16 * i) * PAD + 4 * k4);
#pragma unroll
            for (int j = 0; j < 4; j++)
                vv[j] = *(const float4*)(Vt + (tc + 16 * j) * PAD + 4 * k4);
#pragma unroll
            for (int i = 0; i < 4; i++)
#pragma unroll
                for (int j = 0; j < 4; j++)
                    o[i][j] += pv[i].x * vv[j].x + pv[i].y * vv[j].y
                             + pv[i].z * vv[j].z + pv[i].w * vv[j].w;
        }
        __syncthreads();
    }

    // Normalize and write: [s, NH*HD], head h at col h*64
#pragma unroll
    for (int i = 0; i < 4; i++) {
        float inv = 1.0f / li[i];
#pragma unroll
        for (int j = 0; j < 4; j++)
            out[(size_t)(qt * 64 + tr + 16 * i) * HID + h * HD + tc + 16 * j] = o[i][j] * inv;
    }
}

// ---------------------------------------------------------------------------

extern "C" void kernel_launch(void* const* d_in, const int* in_sizes, int n_in,
                              void* d_out, int out_size)
{
    const float* x      = (const float*)d_in[0];   // [1, 2048, 2048]
    const float* w_qkv  = (const float*)d_in[1];   // [3072, 2048]
    const float* w_o    = (const float*)d_in[2];   // [2048, 2048]
    float* out = (float*)d_out;                    // [1, 2048, 2048]

    float *qkv, *attn;
    cudaGetSymbolAddress((void**)&qkv,  g_qkv);
    cudaGetSymbolAddress((void**)&attn, g_attn);

    // 1) QKV projection: [2048,3072] = x[2048,2048] @ w_qkv[3072,2048]^T
    dim3 g1(QKVD / 128, SEQ / 128);
    sgemm_nt<<<g1, 256>>>(x, w_qkv, qkv, SEQ, QKVD, HID);

    // 2) RoPE in-place on q + k heads
    int nrope = SEQ * (NH + KVH) * 32;
    rope_kernel<<<(nrope + 255) / 256, 256>>>(qkv);

    // 3) Causal GQA flash attention
    size_t smem = (size_t)4 * 64 * PAD * sizeof(float);
    cudaFuncSetAttribute(flash_attn, cudaFuncAttributeMaxDynamicSharedMemorySize, (int)smem);
    dim3 ga(SEQ / 64, NH);
    flash_attn<<<ga, 256, smem>>>(qkv, attn);

    // 4) Output projection: out[2048,2048] = attn @ w_o^T
    dim3 g2(HID / 128, SEQ / 128);
    sgemm_nt<<<g2, 256>>>(attn, w_o, out, SEQ, HID, HID);
}

// round 6
// speedup vs baseline: 1.1279x; 1.1279x over previous
#include <cuda_runtime.h>
#include <cuda_bf16.h>
#include <math.h>

#define SEQ   2048
#define HID   2048
#define NH    32
#define KVH   8
#define HD    64
#define QKVD  3072   // (NH + 2*KVH) * HD

// Scratch (alloc-free rule: device globals)
__device__ float g_qkv[SEQ * QKVD];   // [s, 3072] : q | k | v
__device__ float g_attn[SEQ * HID];   // [s, NH*HD]

// ---------------------------------------------------------------------------
// SGEMM: C[M,N] = A[M,K] * B[N,K]^T   (both row-major, K contiguous)
// 128x128 tile, BK=8, 256 threads, 8x8 micro-tile, software-pipelined gmem.
// ---------------------------------------------------------------------------
__global__ __launch_bounds__(256) void sgemm_nt(
    const float* __restrict__ A, const float* __restrict__ B,
    float* __restrict__ C, int M, int N, int K)
{
    __shared__ float As[8 * 128];   // As[k][row]
    __shared__ float Bs[8 * 128];   // Bs[k][col]

    const int t  = threadIdx.x;
    const int m0 = blockIdx.y * 128;
    const int n0 = blockIdx.x * 128;
    const int tr = t >> 4;          // 0..15 -> rows tr*8..tr*8+7
    const int tc = t & 15;          // 0..15 -> cols tc*8..tc*8+7
    const int lrow = t >> 1;        // 0..127
    const int lk   = (t & 1) * 4;   // 0 or 4

    float acc[8][8];
#pragma unroll
    for (int i = 0; i < 8; i++)
#pragma unroll
        for (int j = 0; j < 8; j++) acc[i][j] = 0.f;

    const float* Ap = A + (size_t)(m0 + lrow) * K + lk;
    const float* Bp = B + (size_t)(n0 + lrow) * K + lk;

    // prefetch first tile
    float4 av = *(const float4*)(Ap);
    float4 bv = *(const float4*)(Bp);

    for (int kb = 0; kb < K; kb += 8) {
        __syncthreads();
        As[(lk + 0) * 128 + lrow] = av.x;
        As[(lk + 1) * 128 + lrow] = av.y;
        As[(lk + 2) * 128 + lrow] = av.z;
        As[(lk + 3) * 128 + lrow] = av.w;
        Bs[(lk + 0) * 128 + lrow] = bv.x;
        Bs[(lk + 1) * 128 + lrow] = bv.y;
        Bs[(lk + 2) * 128 + lrow] = bv.z;
        Bs[(lk + 3) * 128 + lrow] = bv.w;
        __syncthreads();
        // prefetch next tile while computing this one
        if (kb + 8 < K) {
            av = *(const float4*)(Ap + kb + 8);
            bv = *(const float4*)(Bp + kb + 8);
        }
#pragma unroll
        for (int k = 0; k < 8; k++) {
            float4 a0 = *(const float4*)(As + k * 128 + tr * 8);
            float4 a1 = *(const float4*)(As + k * 128 + tr * 8 + 4);
            float4 b0 = *(const float4*)(Bs + k * 128 + tc * 8);
            float4 b1 = *(const float4*)(Bs + k * 128 + tc * 8 + 4);
            float a[8] = {a0.x, a0.y, a0.z, a0.w, a1.x, a1.y, a1.z, a1.w};
            float b[8] = {b0.x, b0.y, b0.z, b0.w, b1.x, b1.y, b1.z, b1.w};
#pragma unroll
            for (int i = 0; i < 8; i++)
#pragma unroll
                for (int j = 0; j < 8; j++)
                    acc[i][j] = fmaf(a[i], b[j], acc[i][j]);
        }
    }

#pragma unroll
    for (int i = 0; i < 8; i++) {
        float* cp = C + (size_t)(m0 + tr * 8 + i) * N + n0 + tc * 8;
        float4 o0 = make_float4(acc[i][0], acc[i][1], acc[i][2], acc[i][3]);
        float4 o1 = make_float4(acc[i][4], acc[i][5], acc[i][6], acc[i][7]);
        *(float4*)(cp)     = o0;
        *(float4*)(cp + 4) = o1;
    }
}

// ---------------------------------------------------------------------------
// RoPE in-place on q (32 heads) and k (8 heads) sections of g_qkv.
// ---------------------------------------------------------------------------
__global__ void rope_kernel(float* __restrict__ qkv)
{
    int idx = blockIdx.x * blockDim.x + threadIdx.x;
    const int total = SEQ * (NH + KVH) * 32;
    if (idx >= total) return;
    int i  = idx & 31;
    int hh = (idx >> 5) % (NH + KVH);
    int s  = idx / ((NH + KVH) * 32);
    size_t base = (size_t)s * QKVD + (hh < NH ? hh * HD : NH * HD + (hh - NH) * HD);
    float inv_freq = 1.0f / powf(10000.0f, (float)i / 32.0f);
    float ang = (float)s * inv_freq;
    float sn, cs;
    sincosf(ang, &sn, &cs);
    float x1 = qkv[base + i];
    float x2 = qkv[base + 32 + i];
    qkv[base + i]      = x1 * cs - x2 * sn;
    qkv[base + 32 + i] = x2 * cs + x1 * sn;
}

// ---------------------------------------------------------------------------
// Causal flash attention v2: fp32, GQA (G=4). BM=128, BN=64, D=64, 128 thr.
// 8x8 micro-tiles, k-major smem layouts (sgemm-style) -> 1.0 B/FMA:
//   Qt[d][q]  (64 x 132), Kt[d][kv] (64 x 68), Vs[kv][d] (64 x 68),
//   Pt[kv][q] (64 x 132) with XOR chunk swizzle (^ kv>>3) for bank-free P.
// Thread (tr=t>>3, tc=t&7): q rows tr*8..+7 ; kv/d cols {tc*4..+3, 32+tc*4..+3}.
// ---------------------------------------------------------------------------
#define QPAD 132
#define KPAD 68

__global__ __launch_bounds__(128, 2) void flash_attn2(
    const float* __restrict__ qkv, float* __restrict__ out)
{
    extern __shared__ float sm[];
    float* Qt = sm;                        // [64][QPAD]
    float* Kt = Qt + 64 * QPAD;            // [64][KPAD]
    float* Vs = Kt + 64 * KPAD;            // [64][KPAD]
    float* Pt = Vs + 64 * KPAD;            // [64][QPAD]

    const int qt = blockIdx.x;             // q tile (128 rows)
    const int h  = blockIdx.y;
    const int kh = h >> 2;
    const int t  = threadIdx.x;
    const int tr = t >> 3;                 // 0..15
    const int tc = t & 7;                  // 0..7

    // Load + transpose Q tile: Qt[d][qrow], one q-row per thread
    {
        const float* qp = qkv + (size_t)(qt * 128 + t) * QKVD + h * HD;
#pragma unroll
        for (int g = 0; g < 16; g++) {
            float4 v = *(const float4*)(qp + 4 * g);
            Qt[(4 * g + 0) * QPAD + t] = v.x;
            Qt[(4 * g + 1) * QPAD + t] = v.y;
            Qt[(4 * g + 2) * QPAD + t] = v.z;
            Qt[(4 * g + 3) * QPAD + t] = v.w;
        }
    }

    float o[8][8];
    float mi[8], li[8];
#pragma unroll
    for (int i = 0; i < 8; i++) {
        mi[i] = -1e30f; li[i] = 0.f;
#pragma unroll
        for (int j = 0; j < 8; j++) o[i][j] = 0.f;
    }

    const int lr = t & 63;                 // loader kv row
    const int lcb = (t >> 6) * 32;         // loader col base (0 / 32)
    const int nj = 2 * qt + 2;

    for (int jt = 0; jt < nj; jt++) {
        __syncthreads();   // Qt ready (first iter) / prev consumers of Kt,Vs,Pt done
        // Load K (transposed) and V (natural) tiles: kv rows jt*64..+63
        {
            const float* kp = qkv + (size_t)(jt * 64 + lr) * QKVD + NH * HD + kh * HD + lcb;
            const float* vp = qkv + (size_t)(jt * 64 + lr) * QKVD + (NH + KVH) * HD + kh * HD + lcb;
#pragma unroll
            for (int g = 0; g < 8; g++) {
                float4 kv4 = *(const float4*)(kp + 4 * g);
                Kt[(lcb + 4 * g + 0) * KPAD + lr] = kv4.x;
                Kt[(lcb + 4 * g + 1) * KPAD + lr] = kv4.y;
                Kt[(lcb + 4 * g + 2) * KPAD + lr] = kv4.z;
                Kt[(lcb + 4 * g + 3) * KPAD + lr] = kv4.w;
                *(float4*)(Vs + lr * KPAD + lcb + 4 * g) = *(const float4*)(vp + 4 * g);
            }
        }
        __syncthreads();

        // ---- QK: s[i][j] = Q[tr*8+i][:] . K[col(j)][:] ----
        float s[8][8];
#pragma unroll
        for (int i = 0; i < 8; i++)
#pragma unroll
            for (int j = 0; j < 8; j++) s[i][j] = 0.f;

#pragma unroll 4
        for (int k = 0; k < 64; k++) {
            float4 a0 = *(const float4*)(Qt + k * QPAD + tr * 8);
            float4 a1 = *(const float4*)(Qt + k * QPAD + tr * 8 + 4);
            float4 b0 = *(const float4*)(Kt + k * KPAD + tc * 4);
            float4 b1 = *(const float4*)(Kt + k * KPAD + tc * 4 + 32);
            float a[8] = {a0.x, a0.y, a0.z, a0.w, a1.x, a1.y, a1.z, a1.w};
            float b[8] = {b0.x, b0.y, b0.z, b0.w, b1.x, b1.y, b1.z, b1.w};
#pragma unroll
            for (int i = 0; i < 8; i++)
#pragma unroll
                for (int j = 0; j < 8; j++)
                    s[i][j] = fmaf(a[i], b[j], s[i][j]);
        }

        // ---- scale + causal mask ----
        const float scale = 0.125f;   // 1/sqrt(64)
        if (jt >= 2 * qt) {           // diagonal-region tiles
#pragma unroll
            for (int i = 0; i < 8; i++) {
                int row = qt * 128 + tr * 8 + i;
#pragma unroll
                for (int j = 0; j < 8; j++) {
                    int col = jt * 64 + ((j >> 2) * 32 + tc * 4 + (j & 3));
                    s[i][j] = (col <= row) ? s[i][j] * scale : -1e30f;
                }
            }
        } else {
#pragma unroll
            for (int i = 0; i < 8; i++)
#pragma unroll
                for (int j = 0; j < 8; j++) s[i][j] *= scale;
        }

        // ---- online softmax (row group = 8 consecutive lanes sharing tr) ----
#pragma unroll
        for (int i = 0; i < 8; i++) {
            float mt = s[i][0];
#pragma unroll
            for (int j = 1; j < 8; j++) mt = fmaxf(mt, s[i][j]);
            mt = fmaxf(mt, __shfl_xor_sync(0xffffffffu, mt, 1));
            mt = fmaxf(mt, __shfl_xor_sync(0xffffffffu, mt, 2));
            mt = fmaxf(mt, __shfl_xor_sync(0xffffffffu, mt, 4));
            float mnew  = fmaxf(mi[i], mt);
            float alpha = __expf(mi[i] - mnew);
            float rs = 0.f;
#pragma unroll
            for (int j = 0; j < 8; j++) {
                float p = __expf(s[i][j] - mnew);
                s[i][j] = p;
                rs += p;
            }
            rs += __shfl_xor_sync(0xffffffffu, rs, 1);
            rs += __shfl_xor_sync(0xffffffffu, rs, 2);
            rs += __shfl_xor_sync(0xffffffffu, rs, 4);
            li[i] = li[i] * alpha + rs;
            mi[i] = mnew;
#pragma unroll
            for (int j = 0; j < 8; j++) o[i][j] *= alpha;
        }

        // ---- store P transposed: Pt[kv][q], chunk-swizzled ----
#pragma unroll
        for (int j = 0; j < 8; j++) {
            int kvloc = (j >> 2) * 32 + tc * 4 + (j & 3);
            int key = kvloc >> 3;
            float4 lo = make_float4(s[0][j], s[1][j], s[2][j], s[3][j]);
            float4 hi = make_float4(s[4][j], s[5][j], s[6][j], s[7][j]);
            *(float4*)(Pt + kvloc * QPAD + (((tr * 2 + 0) ^ key) << 2)) = lo;
            *(float4*)(Pt + kvloc * QPAD + (((tr * 2 + 1) ^ key) << 2)) = hi;
        }
        __syncthreads();

        // ---- PV: o[i][j] += P[tr*8+i][:] . V[:][dcol(j)] ----
#pragma unroll 4
        for (int k = 0; k < 64; k++) {
            int key = k >> 3;
            float4 p0 = *(const float4*)(Pt + k * QPAD + (((tr * 2 + 0) ^ key) << 2));
            float4 p1 = *(const float4*)(Pt + k * QPAD + (((tr * 2 + 1) ^ key) << 2));
            float4 v0 = *(const float4*)(Vs + k * KPAD + tc * 4);
            float4 v1 = *(const float4*)(Vs + k * KPAD + tc * 4 + 32);
            float a[8] = {p0.x, p0.y, p0.z, p0.w, p1.x, p1.y, p1.z, p1.w};
            float b[8] = {v0.x, v0.y, v0.z, v0.w, v1.x, v1.y, v1.z, v1.w};
#pragma unroll
            for (int i = 0; i < 8; i++)
#pragma unroll
                for (int j = 0; j < 8; j++)
                    o[i][j] = fmaf(a[i], b[j], o[i][j]);
        }
    }

    // ---- normalize + write out: row-major [s, NH*HD] ----
#pragma unroll
    for (int i = 0; i < 8; i++) {
        float inv = 1.0f / li[i];
        float* op = out + (size_t)(qt * 128 + tr * 8 + i) * HID + h * HD;
        float4 w0 = make_float4(o[i][0] * inv, o[i][1] * inv, o[i][2] * inv, o[i][3] * inv);
        float4 w1 = make_float4(o[i][4] * inv, o[i][5] * inv, o[i][6] * inv, o[i][7] * inv);
        *(float4*)(op + tc * 4)      = w0;
        *(float4*)(op + 32 + tc * 4) = w1;
    }
}

// ---------------------------------------------------------------------------

extern "C" void kernel_launch(void* const* d_in, const int* in_sizes, int n_in,
                              void* d_out, int out_size)
{
    const float* x      = (const float*)d_in[0];   // [1, 2048, 2048]
    const float* w_qkv  = (const float*)d_in[1];   // [3072, 2048]
    const float* w_o    = (const float*)d_in[2];   // [2048, 2048]
    float* out = (float*)d_out;                    // [1, 2048, 2048]

    float *qkv, *attn;
    cudaGetSymbolAddress((void**)&qkv,  g_qkv);
    cudaGetSymbolAddress((void**)&attn, g_attn);

    // 1) QKV projection: [2048,3072] = x[2048,2048] @ w_qkv[3072,2048]^T
    dim3 g1(QKVD / 128, SEQ / 128);
    sgemm_nt<<<g1, 256>>>(x, w_qkv, qkv, SEQ, QKVD, HID);

    // 2) RoPE in-place on q + k heads
    int nrope = SEQ * (NH + KVH) * 32;
    rope_kernel<<<(nrope + 255) / 256, 256>>>(qkv);

    // 3) Causal GQA flash attention (BM=128, BN=64)
    size_t smem = (size_t)(2 * 64 * QPAD + 2 * 64 * KPAD) * sizeof(float);  // 102400 B
    cudaFuncSetAttribute(flash_attn2, cudaFuncAttributeMaxDynamicSharedMemorySize, (int)smem);
    dim3 ga(SEQ / 128, NH);
    flash_attn2<<<ga, 128, smem>>>(qkv, attn);

    // 4) Output projection: out[2048,2048] = attn @ w_o^T
    dim3 g2(HID / 128, SEQ / 128);
    sgemm_nt<<<g2, 256>>>(attn, w_o, out, SEQ, HID, HID);
}

// round 10
// speedup vs baseline: 1.9474x; 1.7267x over previous
#include <cuda_runtime.h>
#include <cuda_bf16.h>
#include <math.h>
#include <stdint.h>

#define SEQ   2048
#define HID   2048
#define NH    32
#define KVH   8
#define HD    64
#define QKVD  3072   // (NH + 2*KVH) * HD

// Scratch (alloc-free rule: device globals)
__device__ float g_qkv[SEQ * QKVD];   // [s, 3072] : q | k | v
__device__ float g_attn[SEQ * HID];   // [s, NH*HD]

// split-bf16 operand buffers
__device__ __nv_bfloat16 g_xh[SEQ * HID],   g_xl[SEQ * HID];
__device__ __nv_bfloat16 g_wqh[QKVD * HID], g_wql[QKVD * HID];
__device__ __nv_bfloat16 g_woh[HID * HID],  g_wol[HID * HID];
__device__ __nv_bfloat16 g_ah[SEQ * HID],   g_al[SEQ * HID];

// ===========================================================================
// helpers
// ===========================================================================
__device__ __forceinline__ uint32_t smem_u32(const void* p) {
    uint32_t a;
    asm("{ .reg .u64 t; cvta.to.shared.u64 t, %1; cvt.u32.u64 %0, t; }" : "=r"(a) : "l"(p));
    return a;
}
__device__ __forceinline__ uint32_t bpack(__nv_bfloat16 a, __nv_bfloat16 b) {
    __nv_bfloat162 t(a, b);   // a -> low half
    return *reinterpret_cast<uint32_t*>(&t);
}
__device__ __forceinline__ void cp16(uint32_t saddr, const void* g) {
    asm volatile("cp.async.cg.shared.global [%0], [%1], 16;" :: "r"(saddr), "l"(g));
}
#define CP_COMMIT() asm volatile("cp.async.commit_group;" ::: "memory")
#define CP_WAIT(N)  asm volatile("cp.async.wait_group %0;" :: "n"(N) : "memory")

__device__ __forceinline__ void ldmx4(uint32_t* r, uint32_t a) {
    asm volatile("ldmatrix.sync.aligned.m8n8.x4.shared.b16 {%0,%1,%2,%3}, [%4];"
                 : "=r"(r[0]), "=r"(r[1]), "=r"(r[2]), "=r"(r[3]) : "r"(a));
}
__device__ __forceinline__ void mma16816(float* c, const uint32_t* a, const uint32_t* b) {
    asm volatile("mma.sync.aligned.m16n8k16.row.col.f32.bf16.bf16.f32 "
                 "{%0,%1,%2,%3}, {%4,%5,%6,%7}, {%8,%9}, {%0,%1,%2,%3};"
                 : "+f"(c[0]), "+f"(c[1]), "+f"(c[2]), "+f"(c[3])
                 : "r"(a[0]), "r"(a[1]), "r"(a[2]), "r"(a[3]), "r"(b[0]), "r"(b[1]));
}

// 16B-chunk XOR swizzle: row stride 64B (32 bf16), chunk c in 0..3
__device__ __forceinline__ uint32_t swz(uint32_t base, int row, int c) {
    return base + row * 64 + ((c ^ ((row >> 1) & 3)) << 4);
}

// ===========================================================================
// split fp32 -> (hi, lo) bf16
// ===========================================================================
__global__ void split_kernel(const float* __restrict__ in,
                             __nv_bfloat16* __restrict__ hi,
                             __nv_bfloat16* __restrict__ lo, int n)
{
    int i = (blockIdx.x * blockDim.x + threadIdx.x) * 4;
    if (i >= n) return;
    float4 v = *(const float4*)(in + i);
    __nv_bfloat16 h0 = __float2bfloat16_rn(v.x), h1 = __float2bfloat16_rn(v.y);
    __nv_bfloat16 h2 = __float2bfloat16_rn(v.z), h3 = __float2bfloat16_rn(v.w);
    *(uint2*)(hi + i) = make_uint2(bpack(h0, h1), bpack(h2, h3));
    float l0 = v.x - __bfloat162float(h0), l1 = v.y - __bfloat162float(h1);
    float l2 = v.z - __bfloat162float(h2), l3 = v.w - __bfloat162float(h3);
    *(uint2*)(lo + i) = make_uint2(
        bpack(__float2bfloat16_rn(l0), __float2bfloat16_rn(l1)),
        bpack(__float2bfloat16_rn(l2), __float2bfloat16_rn(l3)));
}

// ===========================================================================
// mma.sync split-bf16 GEMM: C[M,N] = A[M,K] * B[N,K]^T  (fp32 result)
// 128x128 CTA tile, KC=32, 2-stage cp.async double buffer, 8 warps (4m x 2n),
// warp tile 32x64 (2 m16-tiles x 8 n8-tiles). 3 passes: AhBh + AlBh + AhBl.
// ===========================================================================
#define KC  32
#define STG 32768
#define OA_H 0
#define OA_L 8192
#define OB_H 16384
#define OB_L 24576

__global__ __launch_bounds__(256) void mma_gemm_nt(
    const __nv_bfloat16* __restrict__ Ah, const __nv_bfloat16* __restrict__ Al,
    const __nv_bfloat16* __restrict__ Bh, const __nv_bfloat16* __restrict__ Bl,
    float* __restrict__ C, int N, int K)
{
    extern __shared__ char smc[];
    const uint32_t sb = smem_u32(smc);
    const int t = threadIdx.x, l = t & 31, w = t >> 5;
    const int m0 = blockIdx.y * 128, n0 = blockIdx.x * 128;
    const int wm = w & 3, wn = w >> 2;

    float acc[2][8][4];
#pragma unroll
    for (int mt = 0; mt < 2; mt++)
#pragma unroll
        for (int nt = 0; nt < 8; nt++)
#pragma unroll
            for (int r = 0; r < 4; r++) acc[mt][nt][r] = 0.f;

    // loader geometry: 256 threads, per 16B chunk: row = t>>2 (+64), c = t&3
    const int lr = t >> 2, lc = t & 3;

    // fragment lane geometry
    const int a_rowit = (l & 7) | (((l >> 3) & 1) << 3);  // 0..15
    const int a_ch    = (l >> 4) & 1;                      // k-half
    const int b_lrow  = l & 7;
    const int b_joff  = (l >> 4) & 1;                      // which n8 of pair
    const int b_ch    = (l >> 3) & 1;                      // k-half

    const int NC = K / KC;

    // ---- stage loader ----
    auto load_stage = [&](int s, int kc) {
        uint32_t base = sb + s * STG;
#pragma unroll
        for (int hfl = 0; hfl < 2; hfl++) {
            int row = lr + hfl * 64;
            size_t ga = (size_t)(m0 + row) * K + kc + lc * 8;
            size_t gb = (size_t)(n0 + row) * K + kc + lc * 8;
            cp16(swz(base + OA_H, row, lc), Ah + ga);
            cp16(swz(base + OA_L, row, lc), Al + ga);
            cp16(swz(base + OB_H, row, lc), Bh + gb);
            cp16(swz(base + OB_L, row, lc), Bl + gb);
        }
    };

    load_stage(0, 0);
    CP_COMMIT();

    for (int cidx = 0; cidx < NC; ++cidx) {
        if (cidx + 1 < NC) {
            load_stage((cidx + 1) & 1, (cidx + 1) * KC);
            CP_COMMIT();
            CP_WAIT(1);
        } else {
            CP_COMMIT();
            CP_WAIT(0);
        }
        __syncthreads();

        uint32_t base = sb + (cidx & 1) * STG;
#pragma unroll
        for (int ks = 0; ks < 2; ks++) {
            const int cA = ks * 2 + a_ch;
            uint32_t afh[2][4], afl[2][4];
#pragma unroll
            for (int mt = 0; mt < 2; mt++) {
                int row = wm * 32 + mt * 16 + a_rowit;
                ldmx4(afh[mt], swz(base + OA_H, row, cA));
                ldmx4(afl[mt], swz(base + OA_L, row, cA));
            }
            const int cB = ks * 2 + b_ch;
#pragma unroll
            for (int jp = 0; jp < 4; jp++) {   // n-tile pairs (2jp, 2jp+1)
                int row = wn * 64 + (2 * jp + b_joff) * 8 + b_lrow;
                uint32_t bfh[4], bfl[4];
                ldmx4(bfh, swz(base + OB_H, row, cB));
#pragma unroll
                for (int mt = 0; mt < 2; mt++) {
                    mma16816(acc[mt][2 * jp + 0], afh[mt], bfh + 0);
                    mma16816(acc[mt][2 * jp + 1], afh[mt], bfh + 2);
                    mma16816(acc[mt][2 * jp + 0], afl[mt], bfh + 0);
                    mma16816(acc[mt][2 * jp + 1], afl[mt], bfh + 2);
                }
                ldmx4(bfl, swz(base + OB_L, row, cB));
#pragma unroll
                for (int mt = 0; mt < 2; mt++) {
                    mma16816(acc[mt][2 * jp + 0], afh[mt], bfl + 0);
                    mma16816(acc[mt][2 * jp + 1], afh[mt], bfl + 2);
                }
            }
        }
        __syncthreads();
    }

    // epilogue: c0,c1 -> (row, col..col+1), c2,c3 -> (row+8, ...)
#pragma unroll
    for (int mt = 0; mt < 2; mt++) {
        int row = m0 + wm * 32 + mt * 16 + (l >> 2);
#pragma unroll
        for (int nt = 0; nt < 8; nt++) {
            int col = n0 + wn * 64 + nt * 8 + (l & 3) * 2;
            *(float2*)(C + (size_t)row * N + col)       = make_float2(acc[mt][nt][0], acc[mt][nt][1]);
            *(float2*)(C + (size_t)(row + 8) * N + col) = make_float2(acc[mt][nt][2], acc[mt][nt][3]);
        }
    }
}

// ---------------------------------------------------------------------------
// RoPE in-place on q (32 heads) and k (8 heads) sections of g_qkv.
// ---------------------------------------------------------------------------
__global__ void rope_kernel(float* __restrict__ qkv)
{
    int idx = blockIdx.x * blockDim.x + threadIdx.x;
    const int total = SEQ * (NH + KVH) * 32;
    if (idx >= total) return;
    int i  = idx & 31;
    int hh = (idx >> 5) % (NH + KVH);
    int s  = idx / ((NH + KVH) * 32);
    size_t base = (size_t)s * QKVD + (hh < NH ? hh * HD : NH * HD + (hh - NH) * HD);
    float inv_freq = 1.0f / powf(10000.0f, (float)i / 32.0f);
    float ang = (float)s * inv_freq;
    float sn, cs;
    sincosf(ang, &sn, &cs);
    float x1 = qkv[base + i];
    float x2 = qkv[base + 32 + i];
    qkv[base + i]      = x1 * cs - x2 * sn;
    qkv[base + 32 + i] = x2 * cs + x1 * sn;
}

// ---------------------------------------------------------------------------
// Causal flash attention v2 (unchanged, known-good): fp32, GQA, BM=128 BN=64.
// ---------------------------------------------------------------------------
#define QPAD 132
#define KPAD 68

__global__ __launch_bounds__(128, 2) void flash_attn2(
    const float* __restrict__ qkv, float* __restrict__ out)
{
    extern __shared__ float sm[];
    float* Qt = sm;                        // [64][QPAD]
    float* Kt = Qt + 64 * QPAD;            // [64][KPAD]
    float* Vs = Kt + 64 * KPAD;            // [64][KPAD]
    float* Pt = Vs + 64 * KPAD;            // [64][QPAD]

    const int qt = blockIdx.x;
    const int h  = blockIdx.y;
    const int kh = h >> 2;
    const int t  = threadIdx.x;
    const int tr = t >> 3;
    const int tc = t & 7;

    {
        const float* qp = qkv + (size_t)(qt * 128 + t) * QKVD + h * HD;
#pragma unroll
        for (int g = 0; g < 16; g++) {
            float4 v = *(const float4*)(qp + 4 * g);
            Qt[(4 * g + 0) * QPAD + t] = v.x;
            Qt[(4 * g + 1) * QPAD + t] = v.y;
            Qt[(4 * g + 2) * QPAD + t] = v.z;
            Qt[(4 * g + 3) * QPAD + t] = v.w;
        }
    }

    float o[8][8];
    float mi[8], li[8];
#pragma unroll
    for (int i = 0; i < 8; i++) {
        mi[i] = -1e30f; li[i] = 0.f;
#pragma unroll
        for (int j = 0; j < 8; j++) o[i][j] = 0.f;
    }

    const int lr = t & 63;
    const int lcb = (t >> 6) * 32;
    const int nj = 2 * qt + 2;

    for (int jt = 0; jt < nj; jt++) {
        __syncthreads();
        {
            const float* kp = qkv + (size_t)(jt * 64 + lr) * QKVD + NH * HD + kh * HD + lcb;
            const float* vp = qkv + (size_t)(jt * 64 + lr) * QKVD + (NH + KVH) * HD + kh * HD + lcb;
#pragma unroll
            for (int g = 0; g < 8; g++) {
                float4 kv4 = *(const float4*)(kp + 4 * g);
                Kt[(lcb + 4 * g + 0) * KPAD + lr] = kv4.x;
                Kt[(lcb + 4 * g + 1) * KPAD + lr] = kv4.y;
                Kt[(lcb + 4 * g + 2) * KPAD + lr] = kv4.z;
                Kt[(lcb + 4 * g + 3) * KPAD + lr] = kv4.w;
                *(float4*)(Vs + lr * KPAD + lcb + 4 * g) = *(const float4*)(vp + 4 * g);
            }
        }
        __syncthreads();

        float s[8][8];
#pragma unroll
        for (int i = 0; i < 8; i++)
#pragma unroll
            for (int j = 0; j < 8; j++) s[i][j] = 0.f;

#pragma unroll 4
        for (int k = 0; k < 64; k++) {
            float4 a0 = *(const float4*)(Qt + k * QPAD + tr * 8);
            float4 a1 = *(const float4*)(Qt + k * QPAD + tr * 8 + 4);
            float4 b0 = *(const float4*)(Kt + k * KPAD + tc * 4);
            float4 b1 = *(const float4*)(Kt + k * KPAD + tc * 4 + 32);
            float a[8] = {a0.x, a0.y, a0.z, a0.w, a1.x, a1.y, a1.z, a1.w};
            float b[8] = {b0.x, b0.y, b0.z, b0.w, b1.x, b1.y, b1.z, b1.w};
#pragma unroll
            for (int i = 0; i < 8; i++)
#pragma unroll
                for (int j = 0; j < 8; j++)
                    s[i][j] = fmaf(a[i], b[j], s[i][j]);
        }

        const float scale = 0.125f;
        if (jt >= 2 * qt) {
#pragma unroll
            for (int i = 0; i < 8; i++) {
                int row = qt * 128 + tr * 8 + i;
#pragma unroll
                for (int j = 0; j < 8; j++) {
                    int col = jt * 64 + ((j >> 2) * 32 + tc * 4 + (j & 3));
                    s[i][j] = (col <= row) ? s[i][j] * scale : -1e30f;
                }
            }
        } else {
#pragma unroll
            for (int i = 0; i < 8; i++)
#pragma unroll
                for (int j = 0; j < 8; j++) s[i][j] *= scale;
        }

#pragma unroll
        for (int i = 0; i < 8; i++) {
            float mt = s[i][0];
#pragma unroll
            for (int j = 1; j < 8; j++) mt = fmaxf(mt, s[i][j]);
            mt = fmaxf(mt, __shfl_xor_sync(0xffffffffu, mt, 1));
            mt = fmaxf(mt, __shfl_xor_sync(0xffffffffu, mt, 2));
            mt = fmaxf(mt, __shfl_xor_sync(0xffffffffu, mt, 4));
            float mnew  = fmaxf(mi[i], mt);
            float alpha = __expf(mi[i] - mnew);
            float rs = 0.f;
#pragma unroll
            for (int j = 0; j < 8; j++) {
                float p = __expf(s[i][j] - mnew);
                s[i][j] = p;
                rs += p;
            }
            rs += __shfl_xor_sync(0xffffffffu, rs, 1);
            rs += __shfl_xor_sync(0xffffffffu, rs, 2);
            rs += __shfl_xor_sync(0xffffffffu, rs, 4);
            li[i] = li[i] * alpha + rs;
            mi[i] = mnew;
#pragma unroll
            for (int j = 0; j < 8; j++) o[i][j] *= alpha;
        }

#pragma unroll
        for (int j = 0; j < 8; j++) {
            int kvloc = (j >> 2) * 32 + tc * 4 + (j & 3);
            int key = kvloc >> 3;
            float4 lo = make_float4(s[0][j], s[1][j], s[2][j], s[3][j]);
            float4 hi = make_float4(s[4][j], s[5][j], s[6][j], s[7][j]);
            *(float4*)(Pt + kvloc * QPAD + (((tr * 2 + 0) ^ key) << 2)) = lo;
            *(float4*)(Pt + kvloc * QPAD + (((tr * 2 + 1) ^ key) << 2)) = hi;
        }
        __syncthreads();

#pragma unroll 4
        for (int k = 0; k < 64; k++) {
            int key = k >> 3;
            float4 p0 = *(const float4*)(Pt + k * QPAD + (((tr * 2 + 0) ^ key) << 2));
            float4 p1 = *(const float4*)(Pt + k * QPAD + (((tr * 2 + 1) ^ key) << 2));
            float4 v0 = *(const float4*)(Vs + k * KPAD + tc * 4);
            float4 v1 = *(const float4*)(Vs + k * KPAD + tc * 4 + 32);
            float a[8] = {p0.x, p0.y, p0.z, p0.w, p1.x, p1.y, p1.z, p1.w};
            float b[8] = {v0.x, v0.y, v0.z, v0.w, v1.x, v1.y, v1.z, v1.w};
#pragma unroll
            for (int i = 0; i < 8; i++)
#pragma unroll
                for (int j = 0; j < 8; j++)
                    o[i][j] = fmaf(a[i], b[j], o[i][j]);
        }
    }

#pragma unroll
    for (int i = 0; i < 8; i++) {
        float inv = 1.0f / li[i];
        float* op = out + (size_t)(qt * 128 + tr * 8 + i) * HID + h * HD;
        float4 w0 = make_float4(o[i][0] * inv, o[i][1] * inv, o[i][2] * inv, o[i][3] * inv);
        float4 w1 = make_float4(o[i][4] * inv, o[i][5] * inv, o[i][6] * inv, o[i][7] * inv);
        *(float4*)(op + tc * 4)      = w0;
        *(float4*)(op + 32 + tc * 4) = w1;
    }
}

// ---------------------------------------------------------------------------

extern "C" void kernel_launch(void* const* d_in, const int* in_sizes, int n_in,
                              void* d_out, int out_size)
{
    const float* x      = (const float*)d_in[0];   // [1, 2048, 2048]
    const float* w_qkv  = (const float*)d_in[1];   // [3072, 2048]
    const float* w_o    = (const float*)d_in[2];   // [2048, 2048]
    float* out = (float*)d_out;                    // [1, 2048, 2048]

    float *qkv, *attn;
    cudaGetSymbolAddress((void**)&qkv,  g_qkv);
    cudaGetSymbolAddress((void**)&attn, g_attn);
    __nv_bfloat16 *xh, *xl, *wqh, *wql, *woh, *wol, *ah, *al;
    cudaGetSymbolAddress((void**)&xh,  g_xh);  cudaGetSymbolAddress((void**)&xl,  g_xl);
    cudaGetSymbolAddress((void**)&wqh, g_wqh); cudaGetSymbolAddress((void**)&wql, g_wql);
    cudaGetSymbolAddress((void**)&woh, g_woh); cudaGetSymbolAddress((void**)&wol, g_wol);
    cudaGetSymbolAddress((void**)&ah,  g_ah);  cudaGetSymbolAddress((void**)&al,  g_al);

    cudaFuncSetAttribute(mma_gemm_nt, cudaFuncAttributeMaxDynamicSharedMemorySize, 2 * STG);

    // 0) split operands to hi/lo bf16
    split_kernel<<<(SEQ * HID / 4 + 255) / 256, 256>>>(x, xh, xl, SEQ * HID);
    split_kernel<<<(QKVD * HID / 4 + 255) / 256, 256>>>(w_qkv, wqh, wql, QKVD * HID);

    // 1) QKV projection: [2048,3072] = x @ w_qkv^T  (mma.sync split-bf16)
    dim3 g1(QKVD / 128, SEQ / 128);
    mma_gemm_nt<<<g1, 256, 2 * STG>>>(xh, xl, wqh, wql, qkv, QKVD, HID);

    // 2) RoPE in-place on q + k heads
    int nrope = SEQ * (NH + KVH) * 32;
    rope_kernel<<<(nrope + 255) / 256, 256>>>(qkv);

    // 3) Causal GQA flash attention (BM=128, BN=64)
    size_t smem = (size_t)(2 * 64 * QPAD + 2 * 64 * KPAD) * sizeof(float);  // 102400 B
    cudaFuncSetAttribute(flash_attn2, cudaFuncAttributeMaxDynamicSharedMemorySize, (int)smem);
    dim3 ga(SEQ / 128, NH);
    flash_attn2<<<ga, 128, smem>>>(qkv, attn);

    // 4) Output projection: out = attn @ w_o^T  (mma.sync split-bf16)
    split_kernel<<<(SEQ * HID / 4 + 255) / 256, 256>>>(attn, ah, al, SEQ * HID);
    split_kernel<<<(HID * HID / 4 + 255) / 256, 256>>>(w_o, woh, wol, HID * HID);
    dim3 g2(HID / 128, SEQ / 128);
    mma_gemm_nt<<<g2, 256, 2 * STG>>>(ah, al, woh, wol, out, HID, HID);
}

// round 12
// speedup vs baseline: 3.1768x; 1.6313x over previous
#include <cuda_runtime.h>
#include <cuda_bf16.h>
#include <math.h>
#include <stdint.h>

#define SEQ   2048
#define HID   2048
#define NH    32
#define KVH   8
#define HD    64
#define QKVD  3072   // (NH + 2*KVH) * HD

// Scratch (alloc-free rule: device globals)
__device__ float g_qkv[SEQ * QKVD];   // [s, 3072] : q | k | v
__device__ float g_attn[SEQ * HID];   // [s, NH*HD]

// split-bf16 operand buffers
__device__ __nv_bfloat16 g_xh[SEQ * HID],    g_xl[SEQ * HID];
__device__ __nv_bfloat16 g_wqh[QKVD * HID],  g_wql[QKVD * HID];
__device__ __nv_bfloat16 g_woh[HID * HID],   g_wol[HID * HID];
__device__ __nv_bfloat16 g_ah[SEQ * HID],    g_al[SEQ * HID];
__device__ __nv_bfloat16 g_qkvh[SEQ * QKVD], g_qkvl[SEQ * QKVD];

// ===========================================================================
// helpers
// ===========================================================================
__device__ __forceinline__ uint32_t smem_u32(const void* p) {
    uint32_t a;
    asm("{ .reg .u64 t; cvta.to.shared.u64 t, %1; cvt.u32.u64 %0, t; }" : "=r"(a) : "l"(p));
    return a;
}
__device__ __forceinline__ uint32_t bpack(__nv_bfloat16 a, __nv_bfloat16 b) {
    __nv_bfloat162 t(a, b);   // a -> low half
    return *reinterpret_cast<uint32_t*>(&t);
}
__device__ __forceinline__ void cp16(uint32_t saddr, const void* g) {
    asm volatile("cp.async.cg.shared.global [%0], [%1], 16;" :: "r"(saddr), "l"(g));
}
#define CP_COMMIT() asm volatile("cp.async.commit_group;" ::: "memory")
#define CP_WAIT(N)  asm volatile("cp.async.wait_group %0;" :: "n"(N) : "memory")

__device__ __forceinline__ void ldmx4(uint32_t* r, uint32_t a) {
    asm volatile("ldmatrix.sync.aligned.m8n8.x4.shared.b16 {%0,%1,%2,%3}, [%4];"
                 : "=r"(r[0]), "=r"(r[1]), "=r"(r[2]), "=r"(r[3]) : "r"(a));
}
__device__ __forceinline__ void ldmx4t(uint32_t* r, uint32_t a) {
    asm volatile("ldmatrix.sync.aligned.m8n8.x4.trans.shared.b16 {%0,%1,%2,%3}, [%4];"
                 : "=r"(r[0]), "=r"(r[1]), "=r"(r[2]), "=r"(r[3]) : "r"(a));
}
__device__ __forceinline__ void mma16816(float* c, const uint32_t* a, const uint32_t* b) {
    asm volatile("mma.sync.aligned.m16n8k16.row.col.f32.bf16.bf16.f32 "
                 "{%0,%1,%2,%3}, {%4,%5,%6,%7}, {%8,%9}, {%0,%1,%2,%3};"
                 : "+f"(c[0]), "+f"(c[1]), "+f"(c[2]), "+f"(c[3])
                 : "r"(a[0]), "r"(a[1]), "r"(a[2]), "r"(a[3]), "r"(b[0]), "r"(b[1]));
}

// 16B-chunk XOR swizzle, 64B rows (GEMM slabs)
__device__ __forceinline__ uint32_t swz(uint32_t base, int row, int c) {
    return base + row * 64 + ((c ^ ((row >> 1) & 3)) << 4);
}
// 16B-chunk XOR swizzle, 128B rows (flash slabs: 64 bf16/row, chunks 0..7)
__device__ __forceinline__ uint32_t swz128(uint32_t base, int row, int c) {
    return base + row * 128 + ((c ^ (row & 7)) << 4);
}

// ===========================================================================
// split fp32 -> (hi, lo) bf16
// ===========================================================================
__global__ void split_kernel(const float* __restrict__ in,
                             __nv_bfloat16* __restrict__ hi,
                             __nv_bfloat16* __restrict__ lo, int n)
{
    int i = (blockIdx.x * blockDim.x + threadIdx.x) * 4;
    if (i >= n) return;
    float4 v = *(const float4*)(in + i);
    __nv_bfloat16 h0 = __float2bfloat16_rn(v.x), h1 = __float2bfloat16_rn(v.y);
    __nv_bfloat16 h2 = __float2bfloat16_rn(v.z), h3 = __float2bfloat16_rn(v.w);
    *(uint2*)(hi + i) = make_uint2(bpack(h0, h1), bpack(h2, h3));
    float l0 = v.x - __bfloat162float(h0), l1 = v.y - __bfloat162float(h1);
    float l2 = v.z - __bfloat162float(h2), l3 = v.w - __bfloat162float(h3);
    *(uint2*)(lo + i) = make_uint2(
        bpack(__float2bfloat16_rn(l0), __float2bfloat16_rn(l1)),
        bpack(__float2bfloat16_rn(l2), __float2bfloat16_rn(l3)));
}

// ===========================================================================
// mma.sync split-bf16 GEMM (unchanged, verified): C = A[M,K] * B[N,K]^T
// ===========================================================================
#define KC  32
#define STG 32768
#define OA_H 0
#define OA_L 8192
#define OB_H 16384
#define OB_L 24576

__global__ __launch_bounds__(256) void mma_gemm_nt(
    const __nv_bfloat16* __restrict__ Ah, const __nv_bfloat16* __restrict__ Al,
    const __nv_bfloat16* __restrict__ Bh, const __nv_bfloat16* __restrict__ Bl,
    float* __restrict__ C, int N, int K)
{
    extern __shared__ char smc[];
    const uint32_t sb = smem_u32(smc);
    const int t = threadIdx.x, l = t & 31, w = t >> 5;
    const int m0 = blockIdx.y * 128, n0 = blockIdx.x * 128;
    const int wm = w & 3, wn = w >> 2;

    float acc[2][8][4];
#pragma unroll
    for (int mt = 0; mt < 2; mt++)
#pragma unroll
        for (int nt = 0; nt < 8; nt++)
#pragma unroll
            for (int r = 0; r < 4; r++) acc[mt][nt][r] = 0.f;

    const int lr = t >> 2, lc = t & 3;
    const int a_rowit = (l & 7) | (((l >> 3) & 1) << 3);
    const int a_ch    = (l >> 4) & 1;
    const int b_lrow  = l & 7;
    const int b_joff  = (l >> 4) & 1;
    const int b_ch    = (l >> 3) & 1;

    const int NC = K / KC;

    auto load_stage = [&](int s, int kc) {
        uint32_t base = sb + s * STG;
#pragma unroll
        for (int hfl = 0; hfl < 2; hfl++) {
            int row = lr + hfl * 64;
            size_t ga = (size_t)(m0 + row) * K + kc + lc * 8;
            size_t gb = (size_t)(n0 + row) * K + kc + lc * 8;
            cp16(swz(base + OA_H, row, lc), Ah + ga);
            cp16(swz(base + OA_L, row, lc), Al + ga);
            cp16(swz(base + OB_H, row, lc), Bh + gb);
            cp16(swz(base + OB_L, row, lc), Bl + gb);
        }
    };

    load_stage(0, 0);
    CP_COMMIT();

    for (int cidx = 0; cidx < NC; ++cidx) {
        if (cidx + 1 < NC) {
            load_stage((cidx + 1) & 1, (cidx + 1) * KC);
            CP_COMMIT();
            CP_WAIT(1);
        } else {
            CP_COMMIT();
            CP_WAIT(0);
        }
        __syncthreads();

        uint32_t base = sb + (cidx & 1) * STG;
#pragma unroll
        for (int ks = 0; ks < 2; ks++) {
            const int cA = ks * 2 + a_ch;
            uint32_t afh[2][4], afl[2][4];
#pragma unroll
            for (int mt = 0; mt < 2; mt++) {
                int row = wm * 32 + mt * 16 + a_rowit;
                ldmx4(afh[mt], swz(base + OA_H, row, cA));
                ldmx4(afl[mt], swz(base + OA_L, row, cA));
            }
            const int cB = ks * 2 + b_ch;
#pragma unroll
            for (int jp = 0; jp < 4; jp++) {
                int row = wn * 64 + (2 * jp + b_joff) * 8 + b_lrow;
                uint32_t bfh[4], bfl[4];
                ldmx4(bfh, swz(base + OB_H, row, cB));
#pragma unroll
                for (int mt = 0; mt < 2; mt++) {
                    mma16816(acc[mt][2 * jp + 0], afh[mt], bfh + 0);
                    mma16816(acc[mt][2 * jp + 1], afh[mt], bfh + 2);
                    mma16816(acc[mt][2 * jp + 0], afl[mt], bfh + 0);
                    mma16816(acc[mt][2 * jp + 1], afl[mt], bfh + 2);
                }
                ldmx4(bfl, swz(base + OB_L, row, cB));
#pragma unroll
                for (int mt = 0; mt < 2; mt++) {
                    mma16816(acc[mt][2 * jp + 0], afh[mt], bfl + 0);
                    mma16816(acc[mt][2 * jp + 1], afh[mt], bfl + 2);
                }
            }
        }
        __syncthreads();
    }

#pragma unroll
    for (int mt = 0; mt < 2; mt++) {
        int row = m0 + wm * 32 + mt * 16 + (l >> 2);
#pragma unroll
        for (int nt = 0; nt < 8; nt++) {
            int col = n0 + wn * 64 + nt * 8 + (l & 3) * 2;
            *(float2*)(C + (size_t)row * N + col)       = make_float2(acc[mt][nt][0], acc[mt][nt][1]);
            *(float2*)(C + (size_t)(row + 8) * N + col) = make_float2(acc[mt][nt][2], acc[mt][nt][3]);
        }
    }
}

// ---------------------------------------------------------------------------
// RoPE in-place on q + k sections of g_qkv (fp32).
// ---------------------------------------------------------------------------
__global__ void rope_kernel(float* __restrict__ qkv)
{
    int idx = blockIdx.x * blockDim.x + threadIdx.x;
    const int total = SEQ * (NH + KVH) * 32;
    if (idx >= total) return;
    int i  = idx & 31;
    int hh = (idx >> 5) % (NH + KVH);
    int s  = idx / ((NH + KVH) * 32);
    size_t base = (size_t)s * QKVD + (hh < NH ? hh * HD : NH * HD + (hh - NH) * HD);
    float inv_freq = 1.0f / powf(10000.0f, (float)i / 32.0f);
    float ang = (float)s * inv_freq;
    float sn, cs;
    sincosf(ang, &sn, &cs);
    float x1 = qkv[base + i];
    float x2 = qkv[base + 32 + i];
    qkv[base + i]      = x1 * cs - x2 * sn;
    qkv[base + 32 + i] = x2 * cs + x1 * sn;
}

// ===========================================================================
// flash_attn3: causal GQA flash attention on mma.sync, split-bf16.
// BM=128, BN=64, 4 warps (warp w owns q rows w*32..+31).
// Smem (98304 B): QH[128][64]bf16, QL | 2 stages of {KH,KL,VH,VL}[64][64]bf16.
// QK: 3 passes (QhKh, QlKh, QhKl). PV: 3 passes (PhVh, PlVh, PhVl); P frags
// built in registers from the score C-frags (layout identity). V via
// ldmatrix.trans from natural [kv][d] slab.
// ===========================================================================
#define FQ_H  0
#define FQ_L  16384
#define FKV0  32768      // + stage*32768
#define FKH   0
#define FKL   8192
#define FVH   16384
#define FVL   24576
#define FSM_TOT 98304

__global__ __launch_bounds__(128, 2) void flash_attn3(
    const __nv_bfloat16* __restrict__ qkvh, const __nv_bfloat16* __restrict__ qkvl,
    float* __restrict__ out)
{
    extern __shared__ char smf[];
    const uint32_t sb = smem_u32(smf);
    const int qt = blockIdx.x, h = blockIdx.y, kh = h >> 2;
    const int t = threadIdx.x, l = t & 31, w = t >> 5;   // w = m-warp

    // fragment lane geometry (identical to verified GEMM)
    const int a_rowit = (l & 7) | (((l >> 3) & 1) << 3);
    const int a_ch    = (l >> 4) & 1;
    const int b_lrow  = l & 7;
    const int b_joff  = (l >> 4) & 1;
    const int b_ch    = (l >> 3) & 1;
    const int v_m     = l >> 3;         // matrix idx for trans V load
    const int v_lr    = l & 7;

    // ---- Q load (once): row t, 8 chunks each for hi/lo ----
    {
        const __nv_bfloat16* qsh = qkvh + (size_t)(qt * 128 + t) * QKVD + h * HD;
        const __nv_bfloat16* qsl = qkvl + (size_t)(qt * 128 + t) * QKVD + h * HD;
#pragma unroll
        for (int c = 0; c < 8; c++) {
            cp16(swz128(sb + FQ_H, t, c), qsh + c * 8);
            cp16(swz128(sb + FQ_L, t, c), qsl + c * 8);
        }
    }

    // ---- KV stage loader: row = t>>1, half = t&1 (chunks half*4..+3) ----
    const int kv_r = t >> 1, kv_hf = t & 1;
    auto load_kv = [&](int s, int jt) {
        uint32_t base = sb + FKV0 + s * 32768;
        size_t roff = (size_t)(jt * 64 + kv_r) * QKVD + kh * HD + kv_hf * 32;
        const __nv_bfloat16* ksh = qkvh + roff + NH * HD;
        const __nv_bfloat16* ksl = qkvl + roff + NH * HD;
        const __nv_bfloat16* vsh = qkvh + roff + (NH + KVH) * HD;
        const __nv_bfloat16* vsl = qkvl + roff + (NH + KVH) * HD;
#pragma unroll
        for (int i = 0; i < 4; i++) {
            int c = kv_hf * 4 + i;
            cp16(swz128(base + FKH, kv_r, c), ksh + i * 8);
            cp16(swz128(base + FKL, kv_r, c), ksl + i * 8);
            cp16(swz128(base + FVH, kv_r, c), vsh + i * 8);
            cp16(swz128(base + FVL, kv_r, c), vsl + i * 8);
        }
    };

    float o_[2][8][4];
    float mi_[2][2], li_[2][2];
#pragma unroll
    for (int mt = 0; mt < 2; mt++) {
        mi_[mt][0] = mi_[mt][1] = -1e30f;
        li_[mt][0] = li_[mt][1] = 0.f;
#pragma unroll
        for (int j = 0; j < 8; j++)
#pragma unroll
            for (int r = 0; r < 4; r++) o_[mt][j][r] = 0.f;
    }

    const int nj = 2 * qt + 2;
    load_kv(0, 0);
    CP_COMMIT();

    for (int jt = 0; jt < nj; jt++) {
        CP_WAIT(0);
        __syncthreads();
        if (jt + 1 < nj) {
            load_kv((jt + 1) & 1, jt + 1);
            CP_COMMIT();
        }
        const uint32_t B = sb + FKV0 + (jt & 1) * 32768;

        // ---- QK (3 passes) ----
        float s_[2][8][4];
#pragma unroll
        for (int mt = 0; mt < 2; mt++)
#pragma unroll
            for (int j = 0; j < 8; j++)
#pragma unroll
                for (int r = 0; r < 4; r++) s_[mt][j][r] = 0.f;

#pragma unroll
        for (int kk = 0; kk < 4; kk++) {
            uint32_t ah[2][4], al[2][4];
#pragma unroll
            for (int mt = 0; mt < 2; mt++) {
                int row = w * 32 + mt * 16 + a_rowit;
                ldmx4(ah[mt], swz128(sb + FQ_H, row, kk * 2 + a_ch));
                ldmx4(al[mt], swz128(sb + FQ_L, row, kk * 2 + a_ch));
            }
#pragma unroll
            for (int jp = 0; jp < 4; jp++) {
                int krow = (2 * jp + b_joff) * 8 + b_lrow;
                uint32_t kf[4];
                ldmx4(kf, swz128(B + FKH, krow, kk * 2 + b_ch));
#pragma unroll
                for (int mt = 0; mt < 2; mt++) {
                    mma16816(s_[mt][2 * jp + 0], ah[mt], kf + 0);
                    mma16816(s_[mt][2 * jp + 1], ah[mt], kf + 2);
                    mma16816(s_[mt][2 * jp + 0], al[mt], kf + 0);
                    mma16816(s_[mt][2 * jp + 1], al[mt], kf + 2);
                }
                ldmx4(kf, swz128(B + FKL, krow, kk * 2 + b_ch));
#pragma unroll
                for (int mt = 0; mt < 2; mt++) {
                    mma16816(s_[mt][2 * jp + 0], ah[mt], kf + 0);
                    mma16816(s_[mt][2 * jp + 1], ah[mt], kf + 2);
                }
            }
        }

        // ---- scale + causal mask ----
        const float scale = 0.125f;
        if (jt >= 2 * qt) {
#pragma unroll
            for (int mt = 0; mt < 2; mt++)
#pragma unroll
                for (int j = 0; j < 8; j++)
#pragma unroll
                    for (int r = 0; r < 4; r++) {
                        int row = qt * 128 + w * 32 + mt * 16 + (l >> 2) + (r >> 1) * 8;
                        int col = jt * 64 + j * 8 + (l & 3) * 2 + (r & 1);
                        s_[mt][j][r] = (col <= row) ? s_[mt][j][r] * scale : -1e30f;
                    }
        } else {
#pragma unroll
            for (int mt = 0; mt < 2; mt++)
#pragma unroll
                for (int j = 0; j < 8; j++)
#pragma unroll
                    for (int r = 0; r < 4; r++) s_[mt][j][r] *= scale;
        }

        // ---- online softmax per row-slot (mt, rg) ----
#pragma unroll
        for (int mt = 0; mt < 2; mt++)
#pragma unroll
            for (int rg = 0; rg < 2; rg++) {
                float mx = s_[mt][0][rg * 2];
#pragma unroll
                for (int j = 0; j < 8; j++) {
                    mx = fmaxf(mx, s_[mt][j][rg * 2]);
                    mx = fmaxf(mx, s_[mt][j][rg * 2 + 1]);
                }
                mx = fmaxf(mx, __shfl_xor_sync(0xffffffffu, mx, 1));
                mx = fmaxf(mx, __shfl_xor_sync(0xffffffffu, mx, 2));
                float mnew  = fmaxf(mi_[mt][rg], mx);
                float alpha = __expf(mi_[mt][rg] - mnew);
                float rs = 0.f;
#pragma unroll
                for (int j = 0; j < 8; j++) {
                    float p0 = __expf(s_[mt][j][rg * 2]     - mnew);
                    float p1 = __expf(s_[mt][j][rg * 2 + 1] - mnew);
                    s_[mt][j][rg * 2]     = p0;
                    s_[mt][j][rg * 2 + 1] = p1;
                    rs += p0 + p1;
                }
                rs += __shfl_xor_sync(0xffffffffu, rs, 1);
                rs += __shfl_xor_sync(0xffffffffu, rs, 2);
                li_[mt][rg] = li_[mt][rg] * alpha + rs;
                mi_[mt][rg] = mnew;
#pragma unroll
                for (int j = 0; j < 8; j++) {
                    o_[mt][j][rg * 2]     *= alpha;
                    o_[mt][j][rg * 2 + 1] *= alpha;
                }
            }

        // ---- PV (3 passes), P frags built in registers ----
#pragma unroll
        for (int kk = 0; kk < 4; kk++) {
            uint32_t ph[2][4], pl[2][4];
#pragma unroll
            for (int mt = 0; mt < 2; mt++) {
#pragma unroll
                for (int half = 0; half < 2; half++) {     // tile 2kk+half
                    const float* sv = s_[mt][2 * kk + half];
                    __nv_bfloat16 h0 = __float2bfloat16_rn(sv[0]);
                    __nv_bfloat16 h1 = __float2bfloat16_rn(sv[1]);
                    __nv_bfloat16 h2 = __float2bfloat16_rn(sv[2]);
                    __nv_bfloat16 h3 = __float2bfloat16_rn(sv[3]);
                    ph[mt][half * 2 + 0] = bpack(h0, h1);   // row-grp0, khalf=half
                    ph[mt][half * 2 + 1] = bpack(h2, h3);   // row-grp1
                    pl[mt][half * 2 + 0] = bpack(
                        __float2bfloat16_rn(sv[0] - __bfloat162float(h0)),
                        __float2bfloat16_rn(sv[1] - __bfloat162float(h1)));
                    pl[mt][half * 2 + 1] = bpack(
                        __float2bfloat16_rn(sv[2] - __bfloat162float(h2)),
                        __float2bfloat16_rn(sv[3] - __bfloat162float(h3)));
                }
                // reorder to A-frag {a0,a1,a2,a3} = {t2kk rg0, t2kk rg1, t2kk+1 rg0, t2kk+1 rg1}
                // already in that order: [0]=t2kk rg0, [1]=t2kk rg1, [2]=t2kk+1 rg0, [3]=t2kk+1 rg1
            }
            int vrow = kk * 16 + (v_m & 1) * 8 + v_lr;
#pragma unroll
            for (int jdp = 0; jdp < 4; jdp++) {
                int vch = 2 * jdp + (v_m >> 1);
                uint32_t vf[4];
                ldmx4t(vf, swz128(B + FVH, vrow, vch));
#pragma unroll
                for (int mt = 0; mt < 2; mt++) {
                    mma16816(o_[mt][2 * jdp + 0], ph[mt], vf + 0);
                    mma16816(o_[mt][2 * jdp + 1], ph[mt], vf + 2);
                    mma16816(o_[mt][2 * jdp + 0], pl[mt], vf + 0);
                    mma16816(o_[mt][2 * jdp + 1], pl[mt], vf + 2);
                }
                ldmx4t(vf, swz128(B + FVL, vrow, vch));
#pragma unroll
                for (int mt = 0; mt < 2; mt++) {
                    mma16816(o_[mt][2 * jdp + 0], ph[mt], vf + 0);
                    mma16816(o_[mt][2 * jdp + 1], ph[mt], vf + 2);
                }
            }
        }
        __syncthreads();   // all warps done with stage before loader overwrite next iter
    }

    // ---- normalize + write ----
#pragma unroll
    for (int mt = 0; mt < 2; mt++) {
        int row0 = qt * 128 + w * 32 + mt * 16 + (l >> 2);
        float inv0 = 1.0f / li_[mt][0];
        float inv1 = 1.0f / li_[mt][1];
#pragma unroll
        for (int jd = 0; jd < 8; jd++) {
            int col = h * HD + jd * 8 + (l & 3) * 2;
            *(float2*)(out + (size_t)row0 * HID + col) =
                make_float2(o_[mt][jd][0] * inv0, o_[mt][jd][1] * inv0);
            *(float2*)(out + (size_t)(row0 + 8) * HID + col) =
                make_float2(o_[mt][jd][2] * inv1, o_[mt][jd][3] * inv1);
        }
    }
}

// ---------------------------------------------------------------------------

extern "C" void kernel_launch(void* const* d_in, const int* in_sizes, int n_in,
                              void* d_out, int out_size)
{
    const float* x      = (const float*)d_in[0];   // [1, 2048, 2048]
    const float* w_qkv  = (const float*)d_in[1];   // [3072, 2048]
    const float* w_o    = (const float*)d_in[2];   // [2048, 2048]
    float* out = (float*)d_out;                    // [1, 2048, 2048]

    float *qkv, *attn;
    cudaGetSymbolAddress((void**)&qkv,  g_qkv);
    cudaGetSymbolAddress((void**)&attn, g_attn);
    __nv_bfloat16 *xh, *xl, *wqh, *wql, *woh, *wol, *ah, *al, *qkvh, *qkvl;
    cudaGetSymbolAddress((void**)&xh,   g_xh);   cudaGetSymbolAddress((void**)&xl,   g_xl);
    cudaGetSymbolAddress((void**)&wqh,  g_wqh);  cudaGetSymbolAddress((void**)&wql,  g_wql);
    cudaGetSymbolAddress((void**)&woh,  g_woh);  cudaGetSymbolAddress((void**)&wol,  g_wol);
    cudaGetSymbolAddress((void**)&ah,   g_ah);   cudaGetSymbolAddress((void**)&al,   g_al);
    cudaGetSymbolAddress((void**)&qkvh, g_qkvh); cudaGetSymbolAddress((void**)&qkvl, g_qkvl);

    cudaFuncSetAttribute(mma_gemm_nt, cudaFuncAttributeMaxDynamicSharedMemorySize, 2 * STG);
    cudaFuncSetAttribute(flash_attn3, cudaFuncAttributeMaxDynamicSharedMemorySize, FSM_TOT);

    // 0) split inputs
    split_kernel<<<(SEQ * HID / 4 + 255) / 256, 256>>>(x, xh, xl, SEQ * HID);
    split_kernel<<<(QKVD * HID / 4 + 255) / 256, 256>>>(w_qkv, wqh, wql, QKVD * HID);

    // 1) QKV projection
    dim3 g1(QKVD / 128, SEQ / 128);
    mma_gemm_nt<<<g1, 256, 2 * STG>>>(xh, xl, wqh, wql, qkv, QKVD, HID);

    // 2) RoPE (fp32, in place)
    int nrope = SEQ * (NH + KVH) * 32;
    rope_kernel<<<(nrope + 255) / 256, 256>>>(qkv);

    // 2b) split post-rope qkv to hi/lo bf16 for the mma flash kernel
    split_kernel<<<(SEQ * QKVD / 4 + 255) / 256, 256>>>(qkv, qkvh, qkvl, SEQ * QKVD);

    // 3) flash attention (mma.sync, split-bf16)
    dim3 ga(SEQ / 128, NH);
    flash_attn3<<<ga, 128, FSM_TOT>>>(qkvh, qkvl, attn);

    // 4) output projection
    split_kernel<<<(SEQ * HID / 4 + 255) / 256, 256>>>(attn, ah, al, SEQ * HID);
    split_kernel<<<(HID * HID / 4 + 255) / 256, 256>>>(w_o, woh, wol, HID * HID);
    dim3 g2(HID / 128, SEQ / 128);
    mma_gemm_nt<<<g2, 256, 2 * STG>>>(ah, al, woh, wol, out, HID, HID);
}

// round 16
// speedup vs baseline: 3.6797x; 1.1583x over previous
#include <cuda_runtime.h>
#include <cuda_bf16.h>
#include <math.h>
#include <stdint.h>

#define SEQ   2048
#define HID   2048
#define NH    32
#define KVH   8
#define HD    64
#define QKVD  3072   // (NH + 2*KVH) * HD

// split-bf16 operand buffers (alloc-free rule: device globals)
__device__ __nv_bfloat16 g_xh[SEQ * HID],    g_xl[SEQ * HID];
__device__ __nv_bfloat16 g_wqh[QKVD * HID],  g_wql[QKVD * HID];
__device__ __nv_bfloat16 g_woh[HID * HID],   g_wol[HID * HID];
__device__ __nv_bfloat16 g_ah[SEQ * HID],    g_al[SEQ * HID];
__device__ __nv_bfloat16 g_qkvh[SEQ * QKVD], g_qkvl[SEQ * QKVD];

// ===========================================================================
// helpers
// ===========================================================================
__device__ __forceinline__ uint32_t smem_u32(const void* p) {
    uint32_t a;
    asm("{ .reg .u64 t; cvta.to.shared.u64 t, %1; cvt.u32.u64 %0, t; }" : "=r"(a) : "l"(p));
    return a;
}
__device__ __forceinline__ uint32_t bpack(__nv_bfloat16 a, __nv_bfloat16 b) {
    __nv_bfloat162 t(a, b);   // a -> low half
    return *reinterpret_cast<uint32_t*>(&t);
}
__device__ __forceinline__ void cp16(uint32_t saddr, const void* g) {
    asm volatile("cp.async.cg.shared.global [%0], [%1], 16;" :: "r"(saddr), "l"(g));
}
#define CP_COMMIT() asm volatile("cp.async.commit_group;" ::: "memory")
#define CP_WAIT(N)  asm volatile("cp.async.wait_group %0;" :: "n"(N) : "memory")

__device__ __forceinline__ void ldmx4(uint32_t* r, uint32_t a) {
    asm volatile("ldmatrix.sync.aligned.m8n8.x4.shared.b16 {%0,%1,%2,%3}, [%4];"
                 : "=r"(r[0]), "=r"(r[1]), "=r"(r[2]), "=r"(r[3]) : "r"(a));
}
__device__ __forceinline__ void ldmx4t(uint32_t* r, uint32_t a) {
    asm volatile("ldmatrix.sync.aligned.m8n8.x4.trans.shared.b16 {%0,%1,%2,%3}, [%4];"
                 : "=r"(r[0]), "=r"(r[1]), "=r"(r[2]), "=r"(r[3]) : "r"(a));
}
__device__ __forceinline__ void mma16816(float* c, const uint32_t* a, const uint32_t* b) {
    asm volatile("mma.sync.aligned.m16n8k16.row.col.f32.bf16.bf16.f32 "
                 "{%0,%1,%2,%3}, {%4,%5,%6,%7}, {%8,%9}, {%0,%1,%2,%3};"
                 : "+f"(c[0]), "+f"(c[1]), "+f"(c[2]), "+f"(c[3])
                 : "r"(a[0]), "r"(a[1]), "r"(a[2]), "r"(a[3]), "r"(b[0]), "r"(b[1]));
}

// 16B-chunk XOR swizzle, 64B rows (GEMM slabs)
__device__ __forceinline__ uint32_t swz(uint32_t base, int row, int c) {
    return base + row * 64 + ((c ^ ((row >> 1) & 3)) << 4);
}
// 16B-chunk XOR swizzle, 128B rows (flash slabs)
__device__ __forceinline__ uint32_t swz128(uint32_t base, int row, int c) {
    return base + row * 128 + ((c ^ (row & 7)) << 4);
}

// ===========================================================================
// split fp32 -> (hi, lo) bf16
// ===========================================================================
__global__ void split_kernel(const float* __restrict__ in,
                             __nv_bfloat16* __restrict__ hi,
                             __nv_bfloat16* __restrict__ lo, int n)
{
    int i = (blockIdx.x * blockDim.x + threadIdx.x) * 4;
    if (i >= n) return;
    float4 v = *(const float4*)(in + i);
    __nv_bfloat16 h0 = __float2bfloat16_rn(v.x), h1 = __float2bfloat16_rn(v.y);
    __nv_bfloat16 h2 = __float2bfloat16_rn(v.z), h3 = __float2bfloat16_rn(v.w);
    *(uint2*)(hi + i) = make_uint2(bpack(h0, h1), bpack(h2, h3));
    float l0 = v.x - __bfloat162float(h0), l1 = v.y - __bfloat162float(h1);
    float l2 = v.z - __bfloat162float(h2), l3 = v.w - __bfloat162float(h3);
    *(uint2*)(lo + i) = make_uint2(
        bpack(__float2bfloat16_rn(l0), __float2bfloat16_rn(l1)),
        bpack(__float2bfloat16_rn(l2), __float2bfloat16_rn(l3)));
}

// ===========================================================================
// mma.sync split-bf16 GEMM, persistent tile loop: C = A[M,K] * B[N,K]^T
// mode 0: write fp32 C.  mode 1: apply RoPE to q/k head cols, split to hi/lo
// bf16 and write Ch/Cl (used for the QKV projection; no fp32 buffer at all).
// ===========================================================================
#define KC  32
#define STG 32768
#define OA_H 0
#define OA_L 8192
#define OB_H 16384
#define OB_L 24576

__global__ __launch_bounds__(256) void mma_gemm_nt(
    const __nv_bfloat16* __restrict__ Ah, const __nv_bfloat16* __restrict__ Al,
    const __nv_bfloat16* __restrict__ Bh, const __nv_bfloat16* __restrict__ Bl,
    float* __restrict__ C,
    __nv_bfloat16* __restrict__ Ch, __nv_bfloat16* __restrict__ Cl,
    int N, int K, int ntiles, int nx, int mode)
{
    extern __shared__ char smc[];
    const uint32_t sb = smem_u32(smc);
    const int t = threadIdx.x, l = t & 31, w = t >> 5;
    const int wm = w & 3, wn = w >> 2;

    const int lr = t >> 2, lc = t & 3;
    const int a_rowit = (l & 7) | (((l >> 3) & 1) << 3);
    const int a_ch    = (l >> 4) & 1;
    const int b_lrow  = l & 7;
    const int b_joff  = (l >> 4) & 1;
    const int b_ch    = (l >> 3) & 1;

    const int NC = K / KC;

    for (int tile = blockIdx.x; tile < ntiles; tile += gridDim.x) {
        const int m0 = (tile / nx) * 128;
        const int n0 = (tile % nx) * 128;

        float acc[2][8][4];
#pragma unroll
        for (int mt = 0; mt < 2; mt++)
#pragma unroll
            for (int nt = 0; nt < 8; nt++)
#pragma unroll
                for (int r = 0; r < 4; r++) acc[mt][nt][r] = 0.f;

        auto load_stage = [&](int s, int kc) {
            uint32_t base = sb + s * STG;
#pragma unroll
            for (int hfl = 0; hfl < 2; hfl++) {
                int row = lr + hfl * 64;
                size_t ga = (size_t)(m0 + row) * K + kc + lc * 8;
                size_t gb = (size_t)(n0 + row) * K + kc + lc * 8;
                cp16(swz(base + OA_H, row, lc), Ah + ga);
                cp16(swz(base + OA_L, row, lc), Al + ga);
                cp16(swz(base + OB_H, row, lc), Bh + gb);
                cp16(swz(base + OB_L, row, lc), Bl + gb);
            }
        };

        load_stage(0, 0);
        CP_COMMIT();

        for (int cidx = 0; cidx < NC; ++cidx) {
            if (cidx + 1 < NC) {
                load_stage((cidx + 1) & 1, (cidx + 1) * KC);
                CP_COMMIT();
                CP_WAIT(1);
            } else {
                CP_COMMIT();
                CP_WAIT(0);
            }
            __syncthreads();

            uint32_t base = sb + (cidx & 1) * STG;
#pragma unroll
            for (int ks = 0; ks < 2; ks++) {
                const int cA = ks * 2 + a_ch;
                uint32_t afh[2][4], afl[2][4];
#pragma unroll
                for (int mt = 0; mt < 2; mt++) {
                    int row = wm * 32 + mt * 16 + a_rowit;
                    ldmx4(afh[mt], swz(base + OA_H, row, cA));
                    ldmx4(afl[mt], swz(base + OA_L, row, cA));
                }
                const int cB = ks * 2 + b_ch;
#pragma unroll
                for (int jp = 0; jp < 4; jp++) {
                    int row = wn * 64 + (2 * jp + b_joff) * 8 + b_lrow;
                    uint32_t bfh[4], bfl[4];
                    ldmx4(bfh, swz(base + OB_H, row, cB));
#pragma unroll
                    for (int mt = 0; mt < 2; mt++) {
                        mma16816(acc[mt][2 * jp + 0], afh[mt], bfh + 0);
                        mma16816(acc[mt][2 * jp + 1], afh[mt], bfh + 2);
                        mma16816(acc[mt][2 * jp + 0], afl[mt], bfh + 0);
                        mma16816(acc[mt][2 * jp + 1], afl[mt], bfh + 2);
                    }
                    ldmx4(bfl, swz(base + OB_L, row, cB));
#pragma unroll
                    for (int mt = 0; mt < 2; mt++) {
                        mma16816(acc[mt][2 * jp + 0], afh[mt], bfl + 0);
                        mma16816(acc[mt][2 * jp + 1], afh[mt], bfl + 2);
                    }
                }
            }
            __syncthreads();
        }

        if (mode == 0) {
#pragma unroll
            for (int mt = 0; mt < 2; mt++) {
                int row = m0 + wm * 32 + mt * 16 + (l >> 2);
#pragma unroll
                for (int nt = 0; nt < 8; nt++) {
                    int col = n0 + wn * 64 + nt * 8 + (l & 3) * 2;
                    *(float2*)(C + (size_t)row * N + col)       = make_float2(acc[mt][nt][0], acc[mt][nt][1]);
                    *(float2*)(C + (size_t)(row + 8) * N + col) = make_float2(acc[mt][nt][2], acc[mt][nt][3]);
                }
            }
        } else {
            // fused RoPE (q/k sections) + hi/lo split epilogue.
            // Warp spans one head (64 aligned cols); pair (i, i+32) lives in
            // acc[mt][nt] / acc[mt][nt+4] of the SAME thread.
            const int col0 = n0 + wn * 64;
            const bool ropesec = col0 < (NH + KVH) * HD;   // q or k head
#pragma unroll
            for (int mt = 0; mt < 2; mt++) {
                int r0 = m0 + wm * 32 + mt * 16 + (l >> 2);
                if (ropesec) {
#pragma unroll
                    for (int nt = 0; nt < 4; nt++) {
#pragma unroll
                        for (int r = 0; r < 4; r++) {
                            int i = nt * 8 + (l & 3) * 2 + (r & 1);
                            int srow = r0 + (r >> 1) * 8;
                            float inv_freq = 1.0f / powf(10000.0f, (float)i / 32.0f);
                            float ang = (float)srow * inv_freq;
                            float sn, cs;
                            sincosf(ang, &sn, &cs);
                            float x1 = acc[mt][nt][r], x2 = acc[mt][nt + 4][r];
                            acc[mt][nt][r]     = x1 * cs - x2 * sn;
                            acc[mt][nt + 4][r] = x2 * cs + x1 * sn;
                        }
                    }
                }
#pragma unroll
                for (int nt = 0; nt < 8; nt++) {
                    int col = col0 + nt * 8 + (l & 3) * 2;
#pragma unroll
                    for (int rh = 0; rh < 2; rh++) {
                        float v0 = acc[mt][nt][rh * 2], v1 = acc[mt][nt][rh * 2 + 1];
                        __nv_bfloat16 h0 = __float2bfloat16_rn(v0);
                        __nv_bfloat16 h1 = __float2bfloat16_rn(v1);
                        size_t off = (size_t)(r0 + rh * 8) * N + col;
                        *(uint32_t*)(Ch + off) = bpack(h0, h1);
                        *(uint32_t*)(Cl + off) = bpack(
                            __float2bfloat16_rn(v0 - __bfloat162float(h0)),
                            __float2bfloat16_rn(v1 - __bfloat162float(h1)));
                    }
                }
            }
        }
    }
}

// ===========================================================================
// flash_attn3: causal GQA flash attention on mma.sync, split-bf16.
// BM=128, BN=64, 4 warps. Epilogue writes hi/lo bf16 (ah/al) directly.
// ===========================================================================
#define FQ_H  0
#define FQ_L  16384
#define FKV0  32768      // + stage*32768
#define FKH   0
#define FKL   8192
#define FVH   16384
#define FVL   24576
#define FSM_TOT 98304

__global__ __launch_bounds__(128, 2) void flash_attn3(
    const __nv_bfloat16* __restrict__ qkvh, const __nv_bfloat16* __restrict__ qkvl,
    __nv_bfloat16* __restrict__ outh, __nv_bfloat16* __restrict__ outl)
{
    extern __shared__ char smf[];
    const uint32_t sb = smem_u32(smf);
    const int h = blockIdx.x;                       // head varies fastest
    const int qt = (int)gridDim.y - 1 - (int)blockIdx.y;  // heavy blocks dispatch first
    const int kh = h >> 2;
    const int t = threadIdx.x, l = t & 31, w = t >> 5;

    const int a_rowit = (l & 7) | (((l >> 3) & 1) << 3);
    const int a_ch    = (l >> 4) & 1;
    const int b_lrow  = l & 7;
    const int b_joff  = (l >> 4) & 1;
    const int b_ch    = (l >> 3) & 1;
    const int v_m     = l >> 3;
    const int v_lr    = l & 7;

    // ---- Q load (once) ----
    {
        const __nv_bfloat16* qsh = qkvh + (size_t)(qt * 128 + t) * QKVD + h * HD;
        const __nv_bfloat16* qsl = qkvl + (size_t)(qt * 128 + t) * QKVD + h * HD;
#pragma unroll
        for (int c = 0; c < 8; c++) {
            cp16(swz128(sb + FQ_H, t, c), qsh + c * 8);
            cp16(swz128(sb + FQ_L, t, c), qsl + c * 8);
        }
    }

    const int kv_r = t >> 1, kv_hf = t & 1;
    auto load_kv = [&](int s, int jt) {
        uint32_t base = sb + FKV0 + s * 32768;
        size_t roff = (size_t)(jt * 64 + kv_r) * QKVD + kh * HD + kv_hf * 32;
        const __nv_bfloat16* ksh = qkvh + roff + NH * HD;
        const __nv_bfloat16* ksl = qkvl + roff + NH * HD;
        const __nv_bfloat16* vsh = qkvh + roff + (NH + KVH) * HD;
        const __nv_bfloat16* vsl = qkvl + roff + (NH + KVH) * HD;
#pragma unroll
        for (int i = 0; i < 4; i++) {
            int c = kv_hf * 4 + i;
            cp16(swz128(base + FKH, kv_r, c), ksh + i * 8);
            cp16(swz128(base + FKL, kv_r, c), ksl + i * 8);
            cp16(swz128(base + FVH, kv_r, c), vsh + i * 8);
            cp16(swz128(base + FVL, kv_r, c), vsl + i * 8);
        }
    };

    float o_[2][8][4];
    float mi_[2][2], li_[2][2];
#pragma unroll
    for (int mt = 0; mt < 2; mt++) {
        mi_[mt][0] = mi_[mt][1] = -1e30f;
        li_[mt][0] = li_[mt][1] = 0.f;
#pragma unroll
        for (int j = 0; j < 8; j++)
#pragma unroll
            for (int r = 0; r < 4; r++) o_[mt][j][r] = 0.f;
    }

    const int nj = 2 * qt + 2;
    load_kv(0, 0);
    CP_COMMIT();

    for (int jt = 0; jt < nj; jt++) {
        CP_WAIT(0);
        __syncthreads();
        if (jt + 1 < nj) {
            load_kv((jt + 1) & 1, jt + 1);
            CP_COMMIT();
        }
        const uint32_t B = sb + FKV0 + (jt & 1) * 32768;

        // ---- QK (3 passes) ----
        float s_[2][8][4];
#pragma unroll
        for (int mt = 0; mt < 2; mt++)
#pragma unroll
            for (int j = 0; j < 8; j++)
#pragma unroll
                for (int r = 0; r < 4; r++) s_[mt][j][r] = 0.f;

#pragma unroll
        for (int kk = 0; kk < 4; kk++) {
            uint32_t ah[2][4], al[2][4];
#pragma unroll
            for (int mt = 0; mt < 2; mt++) {
                int row = w * 32 + mt * 16 + a_rowit;
                ldmx4(ah[mt], swz128(sb + FQ_H, row, kk * 2 + a_ch));
                ldmx4(al[mt], swz128(sb + FQ_L, row, kk * 2 + a_ch));
            }
#pragma unroll
            for (int jp = 0; jp < 4; jp++) {
                int krow = (2 * jp + b_joff) * 8 + b_lrow;
                uint32_t kf[4];
                ldmx4(kf, swz128(B + FKH, krow, kk * 2 + b_ch));
#pragma unroll
                for (int mt = 0; mt < 2; mt++) {
                    mma16816(s_[mt][2 * jp + 0], ah[mt], kf + 0);
                    mma16816(s_[mt][2 * jp + 1], ah[mt], kf + 2);
                    mma16816(s_[mt][2 * jp + 0], al[mt], kf + 0);
                    mma16816(s_[mt][2 * jp + 1], al[mt], kf + 2);
                }
                ldmx4(kf, swz128(B + FKL, krow, kk * 2 + b_ch));
#pragma unroll
                for (int mt = 0; mt < 2; mt++) {
                    mma16816(s_[mt][2 * jp + 0], ah[mt], kf + 0);
                    mma16816(s_[mt][2 * jp + 1], ah[mt], kf + 2);
                }
            }
        }

        // ---- scale + causal mask ----
        const float scale = 0.125f;
        if (jt >= 2 * qt) {
#pragma unroll
            for (int mt = 0; mt < 2; mt++)
#pragma unroll
                for (int j = 0; j < 8; j++)
#pragma unroll
                    for (int r = 0; r < 4; r++) {
                        int row = qt * 128 + w * 32 + mt * 16 + (l >> 2) + (r >> 1) * 8;
                        int col = jt * 64 + j * 8 + (l & 3) * 2 + (r & 1);
                        s_[mt][j][r] = (col <= row) ? s_[mt][j][r] * scale : -1e30f;
                    }
        } else {
#pragma unroll
            for (int mt = 0; mt < 2; mt++)
#pragma unroll
                for (int j = 0; j < 8; j++)
#pragma unroll
                    for (int r = 0; r < 4; r++) s_[mt][j][r] *= scale;
        }

        // ---- online softmax ----
#pragma unroll
        for (int mt = 0; mt < 2; mt++)
#pragma unroll
            for (int rg = 0; rg < 2; rg++) {
                float mx = s_[mt][0][rg * 2];
#pragma unroll
                for (int j = 0; j < 8; j++) {
                    mx = fmaxf(mx, s_[mt][j][rg * 2]);
                    mx = fmaxf(mx, s_[mt][j][rg * 2 + 1]);
                }
                mx = fmaxf(mx, __shfl_xor_sync(0xffffffffu, mx, 1));
                mx = fmaxf(mx, __shfl_xor_sync(0xffffffffu, mx, 2));
                float mnew  = fmaxf(mi_[mt][rg], mx);
                float alpha = __expf(mi_[mt][rg] - mnew);
                float rs = 0.f;
#pragma unroll
                for (int j = 0; j < 8; j++) {
                    float p0 = __expf(s_[mt][j][rg * 2]     - mnew);
                    float p1 = __expf(s_[mt][j][rg * 2 + 1] - mnew);
                    s_[mt][j][rg * 2]     = p0;
                    s_[mt][j][rg * 2 + 1] = p1;
                    rs += p0 + p1;
                }
                rs += __shfl_xor_sync(0xffffffffu, rs, 1);
                rs += __shfl_xor_sync(0xffffffffu, rs, 2);
                li_[mt][rg] = li_[mt][rg] * alpha + rs;
                mi_[mt][rg] = mnew;
#pragma unroll
                for (int j = 0; j < 8; j++) {
                    o_[mt][j][rg * 2]     *= alpha;
                    o_[mt][j][rg * 2 + 1] *= alpha;
                }
            }

        // ---- PV (3 passes), P frags built in registers ----
#pragma unroll
        for (int kk = 0; kk < 4; kk++) {
            uint32_t ph[2][4], pl[2][4];
#pragma unroll
            for (int mt = 0; mt < 2; mt++) {
#pragma unroll
                for (int half = 0; half < 2; half++) {
                    const float* sv = s_[mt][2 * kk + half];
                    __nv_bfloat16 h0 = __float2bfloat16_rn(sv[0]);
                    __nv_bfloat16 h1 = __float2bfloat16_rn(sv[1]);
                    __nv_bfloat16 h2 = __float2bfloat16_rn(sv[2]);
                    __nv_bfloat16 h3 = __float2bfloat16_rn(sv[3]);
                    ph[mt][half * 2 + 0] = bpack(h0, h1);
                    ph[mt][half * 2 + 1] = bpack(h2, h3);
                    pl[mt][half * 2 + 0] = bpack(
                        __float2bfloat16_rn(sv[0] - __bfloat162float(h0)),
                        __float2bfloat16_rn(sv[1] - __bfloat162float(h1)));
                    pl[mt][half * 2 + 1] = bpack(
                        __float2bfloat16_rn(sv[2] - __bfloat162float(h2)),
                        __float2bfloat16_rn(sv[3] - __bfloat162float(h3)));
                }
            }
            int vrow = kk * 16 + (v_m & 1) * 8 + v_lr;
#pragma unroll
            for (int jdp = 0; jdp < 4; jdp++) {
                int vch = 2 * jdp + (v_m >> 1);
                uint32_t vf[4];
                ldmx4t(vf, swz128(B + FVH, vrow, vch));
#pragma unroll
                for (int mt = 0; mt < 2; mt++) {
                    mma16816(o_[mt][2 * jdp + 0], ph[mt], vf + 0);
                    mma16816(o_[mt][2 * jdp + 1], ph[mt], vf + 2);
                    mma16816(o_[mt][2 * jdp + 0], pl[mt], vf + 0);
                    mma16816(o_[mt][2 * jdp + 1], pl[mt], vf + 2);
                }
                ldmx4t(vf, swz128(B + FVL, vrow, vch));
#pragma unroll
                for (int mt = 0; mt < 2; mt++) {
                    mma16816(o_[mt][2 * jdp + 0], ph[mt], vf + 0);
                    mma16816(o_[mt][2 * jdp + 1], ph[mt], vf + 2);
                }
            }
        }
        __syncthreads();
    }

    // ---- normalize + fused hi/lo split write ----
#pragma unroll
    for (int mt = 0; mt < 2; mt++) {
        int row0 = qt * 128 + w * 32 + mt * 16 + (l >> 2);
        float inv0 = 1.0f / li_[mt][0];
        float inv1 = 1.0f / li_[mt][1];
#pragma unroll
        for (int jd = 0; jd < 8; jd++) {
            int col = h * HD + jd * 8 + (l & 3) * 2;
#pragma unroll
            for (int rh = 0; rh < 2; rh++) {
                float inv = rh ? inv1 : inv0;
                float v0 = o_[mt][jd][rh * 2] * inv;
                float v1 = o_[mt][jd][rh * 2 + 1] * inv;
                __nv_bfloat16 h0 = __float2bfloat16_rn(v0);
                __nv_bfloat16 h1 = __float2bfloat16_rn(v1);
                size_t off = (size_t)(row0 + rh * 8) * HID + col;
                *(uint32_t*)(outh + off) = bpack(h0, h1);
                *(uint32_t*)(outl + off) = bpack(
                    __float2bfloat16_rn(v0 - __bfloat162float(h0)),
                    __float2bfloat16_rn(v1 - __bfloat162float(h1)));
            }
        }
    }
}

// ---------------------------------------------------------------------------

extern "C" void kernel_launch(void* const* d_in, const int* in_sizes, int n_in,
                              void* d_out, int out_size)
{
    const float* x      = (const float*)d_in[0];   // [1, 2048, 2048]
    const float* w_qkv  = (const float*)d_in[1];   // [3072, 2048]
    const float* w_o    = (const float*)d_in[2];   // [2048, 2048]
    float* out = (float*)d_out;                    // [1, 2048, 2048]

    __nv_bfloat16 *xh, *xl, *wqh, *wql, *woh, *wol, *ah, *al, *qkvh, *qkvl;
    cudaGetSymbolAddress((void**)&xh,   g_xh);   cudaGetSymbolAddress((void**)&xl,   g_xl);
    cudaGetSymbolAddress((void**)&wqh,  g_wqh);  cudaGetSymbolAddress((void**)&wql,  g_wql);
    cudaGetSymbolAddress((void**)&woh,  g_woh);  cudaGetSymbolAddress((void**)&wol,  g_wol);
    cudaGetSymbolAddress((void**)&ah,   g_ah);   cudaGetSymbolAddress((void**)&al,   g_al);
    cudaGetSymbolAddress((void**)&qkvh, g_qkvh); cudaGetSymbolAddress((void**)&qkvl, g_qkvl);

    cudaFuncSetAttribute(mma_gemm_nt, cudaFuncAttributeMaxDynamicSharedMemorySize, 2 * STG);
    cudaFuncSetAttribute(flash_attn3, cudaFuncAttributeMaxDynamicSharedMemorySize, FSM_TOT);

    const int PGRID = 296;   // 148 SMs x 2 CTAs

    // 0) split inputs
    split_kernel<<<(SEQ * HID / 4 + 255) / 256, 256>>>(x, xh, xl, SEQ * HID);
    split_kernel<<<(QKVD * HID / 4 + 255) / 256, 256>>>(w_qkv, wqh, wql, QKVD * HID);

    // 1) QKV projection + fused RoPE + split (persistent, mode 1)
    mma_gemm_nt<<<PGRID, 256, 2 * STG>>>(xh, xl, wqh, wql,
                                         nullptr, qkvh, qkvl,
                                         QKVD, HID, (QKVD / 128) * (SEQ / 128), QKVD / 128, 1);

    // 2) flash attention (mma.sync, split-bf16), heavy qt first, fused split out
    dim3 ga(NH, SEQ / 128);
    flash_attn3<<<ga, 128, FSM_TOT>>>(qkvh, qkvl, ah, al);

    // 3) output projection (persistent, mode 0)
    split_kernel<<<(HID * HID / 4 + 255) / 256, 256>>>(w_o, woh, wol, HID * HID);
    mma_gemm_nt<<<PGRID, 256, 2 * STG>>>(ah, al, woh, wol,
                                         out, nullptr, nullptr,
                                         HID, HID, (HID / 128) * (SEQ / 128), HID / 128, 0);
}